// round 1
// baseline (speedup 1.0000x reference)
#include <cuda_runtime.h>
#include <cuda_bf16.h>
#include <math.h>

// Problem constants
#define BB   4
#define NH   16
#define HD   64
#define DM   1024
#define LQ   2048
#define LK   2048
#define MTOT (BB * LQ)      // 8192 rows for projection GEMMs

// ---------------------------------------------------------------------------
// Scratch (device globals — no allocation allowed)
// ---------------------------------------------------------------------------
__device__ float g_q[BB * NH * LQ * HD];    // [b,h,l,d] 32MB
__device__ float g_k[BB * NH * LK * HD];
__device__ float g_v[BB * NH * LK * HD];
__device__ float g_ctx[BB * LQ * DM];       // [b,l, h*64+d] 32MB

// ---------------------------------------------------------------------------
// GEMM: C[M,N] = A[M,K] * W[N,K]^T + bias[N]
//   A row-major (K contiguous), W row-major (K contiguous) -> "NT" style.
//   MODE 0: write C[m*DM + n]               (plain, for output projection)
//   MODE 1: scatter to head layout [(b*NH+h)*L + l]*HD + dd  (for q/k/v)
// Tile: BM=128, BN=64, BK=16; 256 threads; 8x4 micro-tile.
// ---------------------------------------------------------------------------
template <int MODE>
__global__ void __launch_bounds__(256)
gemm_bias_kernel(const float* __restrict__ A,
                 const float* __restrict__ W,
                 const float* __restrict__ bias,
                 float* __restrict__ out)
{
    const int BM = 128, BN = 64, BK = 16;
    __shared__ __align__(16) float As[BK][BM];
    __shared__ __align__(16) float Bs[BK][BN];

    const int tid = threadIdx.x;
    const int bm = blockIdx.y * BM;
    const int bn = blockIdx.x * BN;
    const int ty = tid >> 4;       // 0..15  -> rows ty*8 .. ty*8+7
    const int tx = tid & 15;       // 0..15  -> cols tx*4 .. tx*4+3

    float acc[8][4];
#pragma unroll
    for (int i = 0; i < 8; i++)
#pragma unroll
        for (int j = 0; j < 4; j++) acc[i][j] = 0.f;

    // A-load mapping: r = tid>>1 (0..127), c = (tid&1)*8, two float4
    const int ar = tid >> 1;
    const int ac = (tid & 1) * 8;
    // B-load mapping: r = tid>>2 (0..63), c = (tid&3)*4, one float4
    const int br = tid >> 2;
    const int bc = (tid & 3) * 4;

    for (int kt = 0; kt < DM; kt += BK) {
        {
            const float4* src =
                reinterpret_cast<const float4*>(A + (size_t)(bm + ar) * DM + kt + ac);
            float4 v0 = src[0];
            float4 v1 = src[1];
            As[ac + 0][ar] = v0.x; As[ac + 1][ar] = v0.y;
            As[ac + 2][ar] = v0.z; As[ac + 3][ar] = v0.w;
            As[ac + 4][ar] = v1.x; As[ac + 5][ar] = v1.y;
            As[ac + 6][ar] = v1.z; As[ac + 7][ar] = v1.w;
        }
        {
            float4 v = *reinterpret_cast<const float4*>(
                W + (size_t)(bn + br) * DM + kt + bc);
            Bs[bc + 0][br] = v.x; Bs[bc + 1][br] = v.y;
            Bs[bc + 2][br] = v.z; Bs[bc + 3][br] = v.w;
        }
        __syncthreads();

#pragma unroll
        for (int c = 0; c < BK; c++) {
            float4 a0 = *reinterpret_cast<const float4*>(&As[c][ty * 8]);
            float4 a1 = *reinterpret_cast<const float4*>(&As[c][ty * 8 + 4]);
            float4 b0 = *reinterpret_cast<const float4*>(&Bs[c][tx * 4]);
            float a[8] = {a0.x, a0.y, a0.z, a0.w, a1.x, a1.y, a1.z, a1.w};
            float b[4] = {b0.x, b0.y, b0.z, b0.w};
#pragma unroll
            for (int i = 0; i < 8; i++)
#pragma unroll
                for (int j = 0; j < 4; j++)
                    acc[i][j] = fmaf(a[i], b[j], acc[i][j]);
        }
        __syncthreads();
    }

    // Epilogue
#pragma unroll
    for (int i = 0; i < 8; i++) {
        const int m = bm + ty * 8 + i;
#pragma unroll
        for (int j = 0; j < 4; j++) {
            const int n = bn + tx * 4 + j;
            const float val = acc[i][j] + bias[n];
            if (MODE == 0) {
                out[(size_t)m * DM + n] = val;
            } else {
                const int b  = m >> 11;        // m / LQ (LQ = 2048)
                const int l  = m & (LQ - 1);
                const int h  = n >> 6;         // n / HD
                const int dd = n & (HD - 1);
                out[(((size_t)(b * NH + h)) * LQ + l) * HD + dd] = val;
            }
        }
    }
}

// ---------------------------------------------------------------------------
// RoPE (in-place on [B,H,L,HD] tensor; cos/sin are [B,L,HD])
// out[0:32]  = x1*cos - x2*sin ;  out[32:64] = x2*cos + x1*sin
// One thread per (b,h,l,dd<32) pair.
// ---------------------------------------------------------------------------
__global__ void rope_kernel(float* __restrict__ x,
                            const float* __restrict__ cosb,
                            const float* __restrict__ sinb)
{
    const int total = BB * NH * LQ * 32;
    int idx = blockIdx.x * blockDim.x + threadIdx.x;
    if (idx >= total) return;
    const int dd = idx & 31;
    const int l  = (idx >> 5) & (LQ - 1);
    const int h  = (idx >> 16) & (NH - 1);   // 5 + 11 bits
    const int b  = idx >> 20;

    float* xr = x + (((size_t)(b * NH + h)) * LQ + l) * HD;
    const float* cr = cosb + ((size_t)b * LQ + l) * HD;
    const float* sr = sinb + ((size_t)b * LQ + l) * HD;

    const float x1 = xr[dd];
    const float x2 = xr[dd + 32];
    xr[dd]      = x1 * cr[dd]      - x2 * sr[dd];
    xr[dd + 32] = x2 * cr[dd + 32] + x1 * sr[dd + 32];
}

// ---------------------------------------------------------------------------
// Flash attention: per block one (b,h) and one 64-row Q tile.
// BQ=64, BK=32. Online softmax. O kept in registers (4x4 per thread).
// Writes context to g_ctx in [b, l, h*64+dd] layout.
// ---------------------------------------------------------------------------
__global__ void __launch_bounds__(256)
flash_attn_kernel(const float* __restrict__ q,
                  const float* __restrict__ k,
                  const float* __restrict__ v,
                  const unsigned char* __restrict__ mask,
                  float* __restrict__ ctx)
{
    const int BQ = 64, BK2 = 32;
    const float SCALE = 0.125f;   // 1/sqrt(64)

    __shared__ __align__(16) float Qs[BQ][68];
    __shared__ __align__(16) float Ks[BK2][68];
    __shared__ __align__(16) float Vs[BK2][68];
    __shared__ __align__(16) float Ss[BQ][36];
    __shared__ float m_s[BQ], l_s[BQ], scale_s[BQ];
    __shared__ unsigned char msk[BK2];

    const int tid = threadIdx.x;
    const int bh = blockIdx.y;          // b*NH + h
    const int b  = bh >> 4;
    const int h  = bh & 15;
    const int q0 = blockIdx.x * BQ;

    const float* qbase = q + (((size_t)bh) * LQ + q0) * HD;
    const float* kbase = k + ((size_t)bh) * LK * HD;
    const float* vbase = v + ((size_t)bh) * LK * HD;

    // Load Q tile: 64x64 floats -> 1024 float4, 4 per thread
    for (int t = tid; t < BQ * 16; t += 256) {
        const int r  = t >> 4;
        const int c4 = (t & 15) * 4;
        float4 val = *reinterpret_cast<const float4*>(qbase + r * HD + c4);
        Qs[r][c4 + 0] = val.x; Qs[r][c4 + 1] = val.y;
        Qs[r][c4 + 2] = val.z; Qs[r][c4 + 3] = val.w;
    }
    if (tid < BQ) { m_s[tid] = -1e30f; l_s[tid] = 0.f; }

    const int ty = tid >> 4;   // 0..15
    const int tx = tid & 15;   // 0..15
    const int i0 = ty * 4;     // this thread's 4 Q rows
    const int j0 = tx * 2;     // this thread's 2 S cols (per K tile)
    const int d0 = tx * 4;     // this thread's 4 O cols

    float o[4][4];
#pragma unroll
    for (int i = 0; i < 4; i++)
#pragma unroll
        for (int j = 0; j < 4; j++) o[i][j] = 0.f;

    __syncthreads();

    for (int kt = 0; kt < LK; kt += BK2) {
        // Load K,V tiles: each 32x64 = 512 float4, 2 per thread
        for (int t = tid; t < BK2 * 16; t += 256) {
            const int r  = t >> 4;
            const int c4 = (t & 15) * 4;
            float4 kv = *reinterpret_cast<const float4*>(kbase + (size_t)(kt + r) * HD + c4);
            Ks[r][c4 + 0] = kv.x; Ks[r][c4 + 1] = kv.y;
            Ks[r][c4 + 2] = kv.z; Ks[r][c4 + 3] = kv.w;
            float4 vv = *reinterpret_cast<const float4*>(vbase + (size_t)(kt + r) * HD + c4);
            Vs[r][c4 + 0] = vv.x; Vs[r][c4 + 1] = vv.y;
            Vs[r][c4 + 2] = vv.z; Vs[r][c4 + 3] = vv.w;
        }
        if (tid < BK2) msk[tid] = mask[(size_t)b * LK + kt + tid];
        __syncthreads();

        // S = Q * K^T  (4 rows x 2 cols per thread)
        {
            float s[4][2];
#pragma unroll
            for (int i = 0; i < 4; i++) { s[i][0] = 0.f; s[i][1] = 0.f; }
#pragma unroll
            for (int d = 0; d < HD; d += 4) {
                float4 k0 = *reinterpret_cast<const float4*>(&Ks[j0][d]);
                float4 k1 = *reinterpret_cast<const float4*>(&Ks[j0 + 1][d]);
#pragma unroll
                for (int i = 0; i < 4; i++) {
                    float4 qq = *reinterpret_cast<const float4*>(&Qs[i0 + i][d]);
                    s[i][0] += qq.x * k0.x + qq.y * k0.y + qq.z * k0.z + qq.w * k0.w;
                    s[i][1] += qq.x * k1.x + qq.y * k1.y + qq.z * k1.z + qq.w * k1.w;
                }
            }
#pragma unroll
            for (int i = 0; i < 4; i++) {
                Ss[i0 + i][j0]     = msk[j0]     ? -1e30f : s[i][0] * SCALE;
                Ss[i0 + i][j0 + 1] = msk[j0 + 1] ? -1e30f : s[i][1] * SCALE;
            }
        }
        __syncthreads();

        // Row max + rescale factor (64 threads, one row each)
        if (tid < BQ) {
            float mx = m_s[tid];
#pragma unroll
            for (int c = 0; c < BK2; c++) mx = fmaxf(mx, Ss[tid][c]);
            scale_s[tid] = __expf(m_s[tid] - mx);
            m_s[tid] = mx;
        }
        __syncthreads();

        // Exponentiate P = exp(S - m)  (all 256 threads)
        for (int t = tid; t < BQ * BK2; t += 256) {
            const int r = t >> 5;
            const int c = t & 31;
            Ss[r][c] = __expf(Ss[r][c] - m_s[r]);
        }
        __syncthreads();

        // Row sum / l update (concurrent with PV below; only read after barrier)
        if (tid < BQ) {
            float sm = 0.f;
#pragma unroll
            for (int c = 0; c < BK2; c++) sm += Ss[tid][c];
            l_s[tid] = l_s[tid] * scale_s[tid] + sm;
        }

        // Rescale O and accumulate P*V
#pragma unroll
        for (int i = 0; i < 4; i++) {
            const float rs = scale_s[i0 + i];
#pragma unroll
            for (int j = 0; j < 4; j++) o[i][j] *= rs;
        }
#pragma unroll
        for (int j = 0; j < BK2; j++) {
            float4 vv = *reinterpret_cast<const float4*>(&Vs[j][d0]);
#pragma unroll
            for (int i = 0; i < 4; i++) {
                const float p = Ss[i0 + i][j];
                o[i][0] = fmaf(p, vv.x, o[i][0]);
                o[i][1] = fmaf(p, vv.y, o[i][1]);
                o[i][2] = fmaf(p, vv.z, o[i][2]);
                o[i][3] = fmaf(p, vv.w, o[i][3]);
            }
        }
        __syncthreads();
    }

    // Final normalize + write to ctx[b, l, h*64+dd]
#pragma unroll
    for (int i = 0; i < 4; i++) {
        const int r = i0 + i;
        const float inv = 1.f / l_s[r];
        float* dst = ctx + ((size_t)b * LQ + (q0 + r)) * DM + h * HD + d0;
        dst[0] = o[i][0] * inv;
        dst[1] = o[i][1] * inv;
        dst[2] = o[i][2] * inv;
        dst[3] = o[i][3] * inv;
    }
}

// ---------------------------------------------------------------------------
// Launch
// ---------------------------------------------------------------------------
extern "C" void kernel_launch(void* const* d_in, const int* in_sizes, int n_in,
                              void* d_out, int out_size)
{
    const float* query = (const float*)d_in[0];
    const float* key   = (const float*)d_in[1];
    const float* value = (const float*)d_in[2];
    const float* cos_q = (const float*)d_in[3];
    const float* sin_q = (const float*)d_in[4];
    const float* cos_k = (const float*)d_in[5];
    const float* sin_k = (const float*)d_in[6];
    const unsigned char* mask = (const unsigned char*)d_in[7];
    const float* Wq = (const float*)d_in[8];
    const float* bq = (const float*)d_in[9];
    const float* Wk = (const float*)d_in[10];
    const float* bk = (const float*)d_in[11];
    const float* Wv = (const float*)d_in[12];
    const float* bv = (const float*)d_in[13];
    const float* Wo = (const float*)d_in[14];
    const float* bo = (const float*)d_in[15];
    float* out = (float*)d_out;

    float *pq, *pk, *pv, *pctx;
    cudaGetSymbolAddress((void**)&pq,   g_q);
    cudaGetSymbolAddress((void**)&pk,   g_k);
    cudaGetSymbolAddress((void**)&pv,   g_v);
    cudaGetSymbolAddress((void**)&pctx, g_ctx);

    dim3 gg(DM / 64, MTOT / 128);   // (16, 64)

    gemm_bias_kernel<1><<<gg, 256>>>(query, Wq, bq, pq);
    gemm_bias_kernel<1><<<gg, 256>>>(key,   Wk, bk, pk);
    gemm_bias_kernel<1><<<gg, 256>>>(value, Wv, bv, pv);

    const int rope_total = BB * NH * LQ * 32;
    rope_kernel<<<(rope_total + 255) / 256, 256>>>(pq, cos_q, sin_q);
    rope_kernel<<<(rope_total + 255) / 256, 256>>>(pk, cos_k, sin_k);

    flash_attn_kernel<<<dim3(LQ / 64, BB * NH), 256>>>(pq, pk, pv, mask, pctx);

    gemm_bias_kernel<0><<<gg, 256>>>(pctx, Wo, bo, out);
}

// round 4
// speedup vs baseline: 2.7118x; 2.7118x over previous
#include <cuda_runtime.h>
#include <cuda_fp16.h>
#include <math.h>

// Problem constants
#define BB   4
#define NH   16
#define HD   64
#define DM   1024
#define LQ   2048
#define LK   2048
#define MTOT (BB * LQ)

// ---------------------------------------------------------------------------
// Scratch (device globals — no allocation allowed)
// ---------------------------------------------------------------------------
__device__ float g_q[BB * NH * LQ * HD];
__device__ float g_k[BB * NH * LK * HD];
__device__ float g_v[BB * NH * LK * HD];
__device__ float g_ctx[BB * LQ * DM];

// ---------------------------------------------------------------------------
// Helpers
// ---------------------------------------------------------------------------
__device__ __forceinline__ unsigned pack_h2(__half a, __half b) {
    return (unsigned)__half_as_ushort(a) | ((unsigned)__half_as_ushort(b) << 16);
}

// split two floats into (hi half2, lo half2)
__device__ __forceinline__ void split2(float x, float y,
                                       unsigned& hi, unsigned& lo) {
    __half hx = __float2half_rn(x);
    __half hy = __float2half_rn(y);
    __half lx = __float2half_rn(x - __half2float(hx));
    __half ly = __float2half_rn(y - __half2float(hy));
    hi = pack_h2(hx, hy);
    lo = pack_h2(lx, ly);
}

__device__ __forceinline__ void mma_f16(float c[4],
                                        unsigned a0, unsigned a1,
                                        unsigned a2, unsigned a3,
                                        unsigned b0, unsigned b1) {
    asm volatile(
        "mma.sync.aligned.m16n8k16.row.col.f32.f16.f16.f32 "
        "{%0,%1,%2,%3}, {%4,%5,%6,%7}, {%8,%9}, {%0,%1,%2,%3};"
        : "+f"(c[0]), "+f"(c[1]), "+f"(c[2]), "+f"(c[3])
        : "r"(a0), "r"(a1), "r"(a2), "r"(a3), "r"(b0), "r"(b1));
}

// ---------------------------------------------------------------------------
// Split-fp16 GEMM (fp32-accurate): C[M,N] = A[M,K]*W[N,K]^T + bias
// BM=BN=128, BK=32, 4 warps, warp tile 64x64.
// Smem tiles hold half2 (2 k-elements per uint), hi and lo parts.
// MODE 0: plain [m][n];  MODE 1: scatter to [b,h,l,d] head layout.
// ---------------------------------------------------------------------------
template <int MODE>
__global__ void __launch_bounds__(128)
gemm_f16s_kernel(const float* __restrict__ A,
                 const float* __restrict__ W,
                 const float* __restrict__ bias,
                 float* __restrict__ out)
{
    // rows of 16 half2 (= 32 k-elements) + 4 pad
    __shared__ unsigned As_hi[128][20], As_lo[128][20];
    __shared__ unsigned Bs_hi[128][20], Bs_lo[128][20];   // 40 KB total

    const int tid  = threadIdx.x;
    const int warp = tid >> 5;
    const int lane = tid & 31;
    const int g = lane >> 2;
    const int t = lane & 3;
    const int wm = (warp & 1) * 64;
    const int wn = (warp >> 1) * 64;
    const int bm = blockIdx.y * 128;
    const int bn = blockIdx.x * 128;

    float acc[4][8][4];
#pragma unroll
    for (int i = 0; i < 4; i++)
#pragma unroll
        for (int j = 0; j < 8; j++)
#pragma unroll
            for (int c = 0; c < 4; c++) acc[i][j][c] = 0.f;

    for (int kt = 0; kt < DM; kt += 32) {
        // Load 128x32 floats per tile = 1024 float4 ; 8 per thread per tile
#pragma unroll
        for (int p = 0; p < 8; p++) {
            const int idx = tid + p * 128;
            const int m  = idx >> 3;
            const int k4 = (idx & 7) * 4;       // float index
            const int k2 = k4 >> 1;             // half2 index
            {
                float4 v = *reinterpret_cast<const float4*>(
                    A + (size_t)(bm + m) * DM + kt + k4);
                unsigned h0, l0, h1, l1;
                split2(v.x, v.y, h0, l0);
                split2(v.z, v.w, h1, l1);
                *reinterpret_cast<uint2*>(&As_hi[m][k2]) = make_uint2(h0, h1);
                *reinterpret_cast<uint2*>(&As_lo[m][k2]) = make_uint2(l0, l1);
            }
            {
                float4 v = *reinterpret_cast<const float4*>(
                    W + (size_t)(bn + m) * DM + kt + k4);
                unsigned h0, l0, h1, l1;
                split2(v.x, v.y, h0, l0);
                split2(v.z, v.w, h1, l1);
                *reinterpret_cast<uint2*>(&Bs_hi[m][k2]) = make_uint2(h0, h1);
                *reinterpret_cast<uint2*>(&Bs_lo[m][k2]) = make_uint2(l0, l1);
            }
        }
        __syncthreads();

#pragma unroll
        for (int kk = 0; kk < 2; kk++) {        // two K=16 chunks
            const int k0 = kk * 8;              // half2 units
            unsigned ah[4][4], al[4][4];
#pragma unroll
            for (int i = 0; i < 4; i++) {
                const int r0 = wm + 16 * i;
                ah[i][0] = As_hi[r0 + g][k0 + t];
                ah[i][1] = As_hi[r0 + 8 + g][k0 + t];
                ah[i][2] = As_hi[r0 + g][k0 + t + 4];
                ah[i][3] = As_hi[r0 + 8 + g][k0 + t + 4];
                al[i][0] = As_lo[r0 + g][k0 + t];
                al[i][1] = As_lo[r0 + 8 + g][k0 + t];
                al[i][2] = As_lo[r0 + g][k0 + t + 4];
                al[i][3] = As_lo[r0 + 8 + g][k0 + t + 4];
            }
            unsigned bh[8][2], bl[8][2];
#pragma unroll
            for (int j = 0; j < 8; j++) {
                const int n0 = wn + 8 * j;
                bh[j][0] = Bs_hi[n0 + g][k0 + t];
                bh[j][1] = Bs_hi[n0 + g][k0 + t + 4];
                bl[j][0] = Bs_lo[n0 + g][k0 + t];
                bl[j][1] = Bs_lo[n0 + g][k0 + t + 4];
            }
#pragma unroll
            for (int i = 0; i < 4; i++)
#pragma unroll
                for (int j = 0; j < 8; j++) {
                    mma_f16(acc[i][j], ah[i][0], ah[i][1], ah[i][2], ah[i][3],
                            bh[j][0], bh[j][1]);
                    mma_f16(acc[i][j], ah[i][0], ah[i][1], ah[i][2], ah[i][3],
                            bl[j][0], bl[j][1]);
                    mma_f16(acc[i][j], al[i][0], al[i][1], al[i][2], al[i][3],
                            bh[j][0], bh[j][1]);
                }
        }
        __syncthreads();
    }

    // Epilogue: c0,c1 at (g, 2t,2t+1); c2,c3 at (g+8, ...)
#pragma unroll
    for (int i = 0; i < 4; i++) {
#pragma unroll
        for (int j = 0; j < 8; j++) {
            const int n = bn + wn + 8 * j + 2 * t;
            const float b0 = bias[n];
            const float b1 = bias[n + 1];
#pragma unroll
            for (int half = 0; half < 2; half++) {
                const int m = bm + wm + 16 * i + g + half * 8;
                float2 val;
                val.x = acc[i][j][half * 2 + 0] + b0;
                val.y = acc[i][j][half * 2 + 1] + b1;
                if (MODE == 0) {
                    *reinterpret_cast<float2*>(out + (size_t)m * DM + n) = val;
                } else {
                    const int b  = m >> 11;
                    const int l  = m & (LQ - 1);
                    const int h  = n >> 6;
                    const int dd = n & (HD - 1);
                    *reinterpret_cast<float2*>(
                        out + (((size_t)(b * NH + h)) * LQ + l) * HD + dd) = val;
                }
            }
        }
    }
}

// ---------------------------------------------------------------------------
// RoPE (fp32, unchanged)
// ---------------------------------------------------------------------------
__global__ void rope_kernel(float* __restrict__ x,
                            const float* __restrict__ cosb,
                            const float* __restrict__ sinb)
{
    const int total = BB * NH * LQ * 32;
    int idx = blockIdx.x * blockDim.x + threadIdx.x;
    if (idx >= total) return;
    const int dd = idx & 31;
    const int l  = (idx >> 5) & (LQ - 1);
    const int h  = (idx >> 16) & (NH - 1);
    const int b  = idx >> 20;

    float* xr = x + (((size_t)(b * NH + h)) * LQ + l) * HD;
    const float* cr = cosb + ((size_t)b * LQ + l) * HD;
    const float* sr = sinb + ((size_t)b * LQ + l) * HD;

    const float x1 = xr[dd];
    const float x2 = xr[dd + 32];
    xr[dd]      = x1 * cr[dd]      - x2 * sr[dd];
    xr[dd + 32] = x2 * cr[dd + 32] + x1 * sr[dd + 32];
}

// ---------------------------------------------------------------------------
// Flash attention. QK^T in split-fp16 (fp32-accurate); PV in plain fp16.
// One block = (b,h) x 64 Q rows; 4 warps, warp owns 16 rows; BK=32.
// ---------------------------------------------------------------------------
__global__ void __launch_bounds__(128)
flash_f16_kernel(const float* __restrict__ q,
                 const float* __restrict__ k,
                 const float* __restrict__ v,
                 const unsigned char* __restrict__ mask,
                 float* __restrict__ ctx)
{
    __shared__ unsigned Qs_hi[64][36], Qs_lo[64][36];   // 32 half2 + 4 pad
    __shared__ unsigned Ks_hi[32][36], Ks_lo[32][36];
    __shared__ unsigned Vs2[16][72];   // half2(V[2r][n],V[2r+1][n]) at [r][n]
    __shared__ unsigned Ps2[64][20];   // P as half2, 16 half2 + 4 pad
    __shared__ unsigned char msk_s[32];

    const int tid  = threadIdx.x;
    const int warp = tid >> 5;
    const int lane = tid & 31;
    const int g = lane >> 2;
    const int t = lane & 3;
    const int m0 = warp * 16;

    const int bh = blockIdx.y;
    const int b  = bh >> 4;
    const int h  = bh & 15;
    const int q0 = blockIdx.x * 64;

    const float* qbase = q + (((size_t)bh) * LQ + q0) * HD;
    const float* kbase = k + ((size_t)bh) * LK * HD;
    const float* vbase = v + ((size_t)bh) * LK * HD;

    // Load Q tile (scale 1/8 folded — exact power of two)
#pragma unroll
    for (int p = 0; p < 8; p++) {
        const int idx = tid + p * 128;
        const int row = idx >> 4;
        const int d4  = (idx & 15) * 4;
        float4 val = *reinterpret_cast<const float4*>(qbase + row * HD + d4);
        unsigned h0, l0, h1, l1;
        split2(val.x * 0.125f, val.y * 0.125f, h0, l0);
        split2(val.z * 0.125f, val.w * 0.125f, h1, l1);
        *reinterpret_cast<uint2*>(&Qs_hi[row][d4 >> 1]) = make_uint2(h0, h1);
        *reinterpret_cast<uint2*>(&Qs_lo[row][d4 >> 1]) = make_uint2(l0, l1);
    }

    float m_[2] = { -1e30f, -1e30f };
    float l_[2] = { 0.f, 0.f };
    float o[8][4];
#pragma unroll
    for (int n = 0; n < 8; n++)
#pragma unroll
        for (int c = 0; c < 4; c++) o[n][c] = 0.f;

    __half* vsh = reinterpret_cast<__half*>(&Vs2[0][0]);

    for (int kt = 0; kt < LK; kt += 32) {
        __syncthreads();   // previous iter reads done (covers Q load on iter 0)
        // Load K (split) and V (plain) tiles: 32x64 each
#pragma unroll
        for (int p = 0; p < 4; p++) {
            const int idx = tid + p * 128;
            const int row = idx >> 4;
            const int d4  = (idx & 15) * 4;
            {
                float4 kv = *reinterpret_cast<const float4*>(
                    kbase + (size_t)(kt + row) * HD + d4);
                unsigned h0, l0, h1, l1;
                split2(kv.x, kv.y, h0, l0);
                split2(kv.z, kv.w, h1, l1);
                *reinterpret_cast<uint2*>(&Ks_hi[row][d4 >> 1]) = make_uint2(h0, h1);
                *reinterpret_cast<uint2*>(&Ks_lo[row][d4 >> 1]) = make_uint2(l0, l1);
            }
            {
                float4 vv = *reinterpret_cast<const float4*>(
                    vbase + (size_t)(kt + row) * HD + d4);
                const int rbase = (row >> 1) * 144 + (row & 1);
                vsh[rbase + (d4 + 0) * 2] = __float2half_rn(vv.x);
                vsh[rbase + (d4 + 1) * 2] = __float2half_rn(vv.y);
                vsh[rbase + (d4 + 2) * 2] = __float2half_rn(vv.z);
                vsh[rbase + (d4 + 3) * 2] = __float2half_rn(vv.w);
            }
        }
        if (tid < 32) msk_s[tid] = mask[(size_t)b * LK + kt + tid];
        __syncthreads();

        // S = Q*K^T : split-fp16, 4 k-chunks (K=64), 4 n-tiles (32 keys)
        float s[4][4];
#pragma unroll
        for (int j = 0; j < 4; j++)
#pragma unroll
            for (int c = 0; c < 4; c++) s[j][c] = 0.f;
#pragma unroll
        for (int kk = 0; kk < 4; kk++) {
            const int k0 = kk * 8;
            unsigned ah0 = Qs_hi[m0 + g][k0 + t];
            unsigned ah1 = Qs_hi[m0 + 8 + g][k0 + t];
            unsigned ah2 = Qs_hi[m0 + g][k0 + t + 4];
            unsigned ah3 = Qs_hi[m0 + 8 + g][k0 + t + 4];
            unsigned al0 = Qs_lo[m0 + g][k0 + t];
            unsigned al1 = Qs_lo[m0 + 8 + g][k0 + t];
            unsigned al2 = Qs_lo[m0 + g][k0 + t + 4];
            unsigned al3 = Qs_lo[m0 + 8 + g][k0 + t + 4];
#pragma unroll
            for (int j = 0; j < 4; j++) {
                unsigned bh0 = Ks_hi[j * 8 + g][k0 + t];
                unsigned bh1 = Ks_hi[j * 8 + g][k0 + t + 4];
                unsigned bl0 = Ks_lo[j * 8 + g][k0 + t];
                unsigned bl1 = Ks_lo[j * 8 + g][k0 + t + 4];
                mma_f16(s[j], ah0, ah1, ah2, ah3, bh0, bh1);
                mma_f16(s[j], ah0, ah1, ah2, ah3, bl0, bl1);
                mma_f16(s[j], al0, al1, al2, al3, bh0, bh1);
            }
        }

        // Mask
#pragma unroll
        for (int j = 0; j < 4; j++) {
            const int col = j * 8 + 2 * t;
            if (msk_s[col])     { s[j][0] = -1e30f; s[j][2] = -1e30f; }
            if (msk_s[col + 1]) { s[j][1] = -1e30f; s[j][3] = -1e30f; }
        }

        // Row max across quad
        float r0 = fmaxf(fmaxf(s[0][0], s[0][1]), fmaxf(s[1][0], s[1][1]));
        r0 = fmaxf(r0, fmaxf(fmaxf(s[2][0], s[2][1]), fmaxf(s[3][0], s[3][1])));
        float r1 = fmaxf(fmaxf(s[0][2], s[0][3]), fmaxf(s[1][2], s[1][3]));
        r1 = fmaxf(r1, fmaxf(fmaxf(s[2][2], s[2][3]), fmaxf(s[3][2], s[3][3])));
        r0 = fmaxf(r0, __shfl_xor_sync(0xffffffffu, r0, 1));
        r0 = fmaxf(r0, __shfl_xor_sync(0xffffffffu, r0, 2));
        r1 = fmaxf(r1, __shfl_xor_sync(0xffffffffu, r1, 1));
        r1 = fmaxf(r1, __shfl_xor_sync(0xffffffffu, r1, 2));

        const float mn0 = fmaxf(m_[0], r0);
        const float mn1 = fmaxf(m_[1], r1);
        const float alpha0 = __expf(m_[0] - mn0);
        const float alpha1 = __expf(m_[1] - mn1);
        m_[0] = mn0; m_[1] = mn1;

        // P = exp(S - m), row sums
        float sum0 = 0.f, sum1 = 0.f;
#pragma unroll
        for (int j = 0; j < 4; j++) {
            s[j][0] = __expf(s[j][0] - mn0);
            s[j][1] = __expf(s[j][1] - mn0);
            s[j][2] = __expf(s[j][2] - mn1);
            s[j][3] = __expf(s[j][3] - mn1);
            sum0 += s[j][0] + s[j][1];
            sum1 += s[j][2] + s[j][3];
        }
        sum0 += __shfl_xor_sync(0xffffffffu, sum0, 1);
        sum0 += __shfl_xor_sync(0xffffffffu, sum0, 2);
        sum1 += __shfl_xor_sync(0xffffffffu, sum1, 1);
        sum1 += __shfl_xor_sync(0xffffffffu, sum1, 2);
        l_[0] = l_[0] * alpha0 + sum0;
        l_[1] = l_[1] * alpha1 + sum1;

        // Store P (half2) to warp-private band
#pragma unroll
        for (int j = 0; j < 4; j++) {
            Ps2[m0 + g][j * 4 + t] =
                pack_h2(__float2half_rn(s[j][0]), __float2half_rn(s[j][1]));
            Ps2[m0 + 8 + g][j * 4 + t] =
                pack_h2(__float2half_rn(s[j][2]), __float2half_rn(s[j][3]));
        }
        __syncwarp();

        // Rescale O
#pragma unroll
        for (int n = 0; n < 8; n++) {
            o[n][0] *= alpha0; o[n][1] *= alpha0;
            o[n][2] *= alpha1; o[n][3] *= alpha1;
        }

        // O += P * V : plain fp16, 2 k-chunks (32 keys), 8 n-tiles (HD=64)
#pragma unroll
        for (int kk = 0; kk < 2; kk++) {
            const int k0 = kk * 8;
            unsigned a0 = Ps2[m0 + g][k0 + t];
            unsigned a1 = Ps2[m0 + 8 + g][k0 + t];
            unsigned a2 = Ps2[m0 + g][k0 + t + 4];
            unsigned a3 = Ps2[m0 + 8 + g][k0 + t + 4];
#pragma unroll
            for (int n = 0; n < 8; n++) {
                unsigned b0 = Vs2[k0 + t][n * 8 + g];
                unsigned b1 = Vs2[k0 + t + 4][n * 8 + g];
                mma_f16(o[n], a0, a1, a2, a3, b0, b1);
            }
        }
    }

    // Epilogue: normalize and write ctx[b, l, h*64 + d]
    const float inv0 = 1.f / l_[0];
    const float inv1 = 1.f / l_[1];
#pragma unroll
    for (int n = 0; n < 8; n++) {
        const int col = h * HD + n * 8 + 2 * t;
        const int row0 = q0 + m0 + g;
        float2 v0 = { o[n][0] * inv0, o[n][1] * inv0 };
        *reinterpret_cast<float2*>(
            ctx + ((size_t)b * LQ + row0) * DM + col) = v0;
        float2 v1 = { o[n][2] * inv1, o[n][3] * inv1 };
        *reinterpret_cast<float2*>(
            ctx + ((size_t)b * LQ + row0 + 8) * DM + col) = v1;
    }
}

// ---------------------------------------------------------------------------
// Launch
// ---------------------------------------------------------------------------
extern "C" void kernel_launch(void* const* d_in, const int* in_sizes, int n_in,
                              void* d_out, int out_size)
{
    const float* query = (const float*)d_in[0];
    const float* key   = (const float*)d_in[1];
    const float* value = (const float*)d_in[2];
    const float* cos_q = (const float*)d_in[3];
    const float* sin_q = (const float*)d_in[4];
    const float* cos_k = (const float*)d_in[5];
    const float* sin_k = (const float*)d_in[6];
    const unsigned char* mask = (const unsigned char*)d_in[7];
    const float* Wq = (const float*)d_in[8];
    const float* bq = (const float*)d_in[9];
    const float* Wk = (const float*)d_in[10];
    const float* bk = (const float*)d_in[11];
    const float* Wv = (const float*)d_in[12];
    const float* bv = (const float*)d_in[13];
    const float* Wo = (const float*)d_in[14];
    const float* bo = (const float*)d_in[15];
    float* out = (float*)d_out;

    float *pq, *pk, *pv, *pctx;
    cudaGetSymbolAddress((void**)&pq,   g_q);
    cudaGetSymbolAddress((void**)&pk,   g_k);
    cudaGetSymbolAddress((void**)&pv,   g_v);
    cudaGetSymbolAddress((void**)&pctx, g_ctx);

    dim3 gg(DM / 128, MTOT / 128);   // (8, 64)

    gemm_f16s_kernel<1><<<gg, 128>>>(query, Wq, bq, pq);
    gemm_f16s_kernel<1><<<gg, 128>>>(key,   Wk, bk, pk);
    gemm_f16s_kernel<1><<<gg, 128>>>(value, Wv, bv, pv);

    const int rope_total = BB * NH * LQ * 32;
    rope_kernel<<<(rope_total + 255) / 256, 256>>>(pq, cos_q, sin_q);
    rope_kernel<<<(rope_total + 255) / 256, 256>>>(pk, cos_k, sin_k);

    flash_f16_kernel<<<dim3(LQ / 64, BB * NH), 128>>>(pq, pk, pv, mask, pctx);

    gemm_f16s_kernel<0><<<gg, 128>>>(pctx, Wo, bo, out);
}

// round 6
// speedup vs baseline: 3.7070x; 1.3670x over previous
#include <cuda_runtime.h>
#include <cuda_fp16.h>
#include <math.h>
#include <stdint.h>

// Problem constants
#define BB   4
#define NH   16
#define HD   64
#define DM   1024
#define LQ   2048
#define LK   2048
#define MTOT (BB * LQ)

// ---------------------------------------------------------------------------
// Scratch (device globals — no allocation allowed)
// ---------------------------------------------------------------------------
__device__ float g_q[BB * NH * LQ * HD];
__device__ float g_k[BB * NH * LK * HD];
__device__ float g_v[BB * NH * LK * HD];
__device__ float g_ctx[BB * LQ * DM];
__device__ __half g_ahi[MTOT * DM];
__device__ __half g_alo[MTOT * DM];
__device__ __half g_whi[DM * DM];
__device__ __half g_wlo[DM * DM];
__device__ __half g_qhi[BB * NH * LQ * HD];
__device__ __half g_qlo[BB * NH * LQ * HD];
__device__ __half g_khi[BB * NH * LK * HD];
__device__ __half g_klo[BB * NH * LK * HD];
__device__ __half g_vh [BB * NH * LK * HD];

// ---------------------------------------------------------------------------
// Helpers
// ---------------------------------------------------------------------------
__device__ __forceinline__ unsigned pack_h2(__half a, __half b) {
    return (unsigned)__half_as_ushort(a) | ((unsigned)__half_as_ushort(b) << 16);
}

__device__ __forceinline__ void split2(float x, float y,
                                       unsigned& hi, unsigned& lo) {
    __half hx = __float2half_rn(x);
    __half hy = __float2half_rn(y);
    __half lx = __float2half_rn(x - __half2float(hx));
    __half ly = __float2half_rn(y - __half2float(hy));
    hi = pack_h2(hx, hy);
    lo = pack_h2(lx, ly);
}

__device__ __forceinline__ void mma_f16(float c[4],
                                        unsigned a0, unsigned a1,
                                        unsigned a2, unsigned a3,
                                        unsigned b0, unsigned b1) {
    asm volatile(
        "mma.sync.aligned.m16n8k16.row.col.f32.f16.f16.f32 "
        "{%0,%1,%2,%3}, {%4,%5,%6,%7}, {%8,%9}, {%0,%1,%2,%3};"
        : "+f"(c[0]), "+f"(c[1]), "+f"(c[2]), "+f"(c[3])
        : "r"(a0), "r"(a1), "r"(a2), "r"(a3), "r"(b0), "r"(b1));
}

__device__ __forceinline__ uint32_t smem_u32(const void* p) {
    uint32_t a;
    asm("{ .reg .u64 t; cvta.to.shared.u64 t, %1; cvt.u32.u64 %0, t; }"
        : "=r"(a) : "l"(p));
    return a;
}

__device__ __forceinline__ void ldsm_x4(uint32_t addr, unsigned& r0,
                                        unsigned& r1, unsigned& r2,
                                        unsigned& r3) {
    asm volatile(
        "ldmatrix.sync.aligned.m8n8.x4.shared.b16 {%0,%1,%2,%3}, [%4];"
        : "=r"(r0), "=r"(r1), "=r"(r2), "=r"(r3) : "r"(addr));
}

__device__ __forceinline__ void ldsm_x4_t(uint32_t addr, unsigned& r0,
                                          unsigned& r1, unsigned& r2,
                                          unsigned& r3) {
    asm volatile(
        "ldmatrix.sync.aligned.m8n8.x4.trans.shared.b16 {%0,%1,%2,%3}, [%4];"
        : "=r"(r0), "=r"(r1), "=r"(r2), "=r"(r3) : "r"(addr));
}

__device__ __forceinline__ void cpa16(uint32_t dst, const void* src) {
    asm volatile("cp.async.cg.shared.global [%0], [%1], 16;"
                 :: "r"(dst), "l"(src) : "memory");
}
__device__ __forceinline__ void cp_commit() {
    asm volatile("cp.async.commit_group;" ::: "memory");
}
__device__ __forceinline__ void cp_waitall() {
    asm volatile("cp.async.wait_group 0;" ::: "memory");
}

// ---------------------------------------------------------------------------
// Pre-split kernels
// ---------------------------------------------------------------------------
__global__ void split_kernel(const float4* __restrict__ src,
                             uint2* __restrict__ hi,
                             uint2* __restrict__ lo, int n4)
{
    int i = blockIdx.x * blockDim.x + threadIdx.x;
    if (i >= n4) return;
    float4 v = src[i];
    unsigned h0, l0, h1, l1;
    split2(v.x, v.y, h0, l0);
    split2(v.z, v.w, h1, l1);
    hi[i] = make_uint2(h0, h1);
    lo[i] = make_uint2(l0, l1);
}

// RoPE fused with split: reads fp32 [b,h,l,d], writes hi/lo fp16 (scale folded)
__global__ void rope_split_kernel(const float* __restrict__ x,
                                  const float* __restrict__ cosb,
                                  const float* __restrict__ sinb,
                                  __half* __restrict__ hi,
                                  __half* __restrict__ lo, float scale)
{
    const int total = BB * NH * LQ * 32;
    int idx = blockIdx.x * blockDim.x + threadIdx.x;
    if (idx >= total) return;
    const int dd = idx & 31;
    const int l  = (idx >> 5) & (LQ - 1);
    const int h  = (idx >> 16) & (NH - 1);
    const int b  = idx >> 20;

    const size_t rowoff = (((size_t)(b * NH + h)) * LQ + l) * HD;
    const float* xr = x + rowoff;
    const float* cr = cosb + ((size_t)b * LQ + l) * HD;
    const float* sr = sinb + ((size_t)b * LQ + l) * HD;

    const float x1 = xr[dd];
    const float x2 = xr[dd + 32];
    const float y1 = (x1 * cr[dd]      - x2 * sr[dd])      * scale;
    const float y2 = (x2 * cr[dd + 32] + x1 * sr[dd + 32]) * scale;

    __half h1 = __float2half_rn(y1);
    __half h2 = __float2half_rn(y2);
    hi[rowoff + dd]      = h1;
    hi[rowoff + dd + 32] = h2;
    lo[rowoff + dd]      = __float2half_rn(y1 - __half2float(h1));
    lo[rowoff + dd + 32] = __float2half_rn(y2 - __half2float(h2));
}

// Plain fp32 -> fp16 convert (for V)
__global__ void vconv_kernel(const float4* __restrict__ src,
                             uint2* __restrict__ dst, int n4)
{
    int i = blockIdx.x * blockDim.x + threadIdx.x;
    if (i >= n4) return;
    float4 v = src[i];
    dst[i] = make_uint2(
        pack_h2(__float2half_rn(v.x), __float2half_rn(v.y)),
        pack_h2(__float2half_rn(v.z), __float2half_rn(v.w)));
}

// ---------------------------------------------------------------------------
// Split-fp16 GEMM with cp.async double-buffer + ldmatrix fragment loads.
// C[M,N] = A[M,K]*W[N,K]^T + bias.  Tile 128x128, K-stage 32 halves,
// 4 warps, warp tile 64x64 (warp grid 2x2). Row stride 40 halves (80B,
// ldmatrix conflict-free).
// MODE 0: plain [m][n];  MODE 1: scatter to [b,h,l,d] head layout.
// ---------------------------------------------------------------------------
#define G_STAGE 40960          // bytes per stage (4 arrays x 10240)
#define G_AHI   0
#define G_ALO   10240
#define G_BHI   20480
#define G_BLO   30720
#define G_SMEM  (2 * G_STAGE)  // 81920

template <int MODE>
__global__ void __launch_bounds__(128)
gemm_cp_kernel(const __half* __restrict__ Ahi, const __half* __restrict__ Alo,
               const __half* __restrict__ Whi, const __half* __restrict__ Wlo,
               const float* __restrict__ bias, float* __restrict__ out)
{
    extern __shared__ __align__(128) char smem[];
    const int tid  = threadIdx.x;
    const int warp = tid >> 5;
    const int lane = tid & 31;
    const int g = lane >> 2;
    const int t = lane & 3;
    const int wm = (warp & 1) * 64;
    const int wn = (warp >> 1) * 64;
    const int bm = blockIdx.y * 128;
    const int bn = blockIdx.x * 128;
    const uint32_t sb = smem_u32(smem);

    float acc[4][8][4];
#pragma unroll
    for (int i = 0; i < 4; i++)
#pragma unroll
        for (int j = 0; j < 8; j++)
#pragma unroll
            for (int c = 0; c < 4; c++) acc[i][j][c] = 0.f;

    // stage loader
    const int lrow = tid >> 2;          // 0..31 base row (advances by 32)
    const int lch  = tid & 3;           // 16B chunk within 64B row
#define G_ISSUE(IT)                                                          \
    do {                                                                     \
        const int kt_ = (IT) * 32;                                           \
        const uint32_t base_ = sb + ((IT) & 1) * G_STAGE;                    \
        _Pragma("unroll")                                                    \
        for (int p_ = 0; p_ < 4; p_++) {                                     \
            const int row_ = lrow + p_ * 32;                                 \
            const uint32_t d_ = row_ * 80 + lch * 16;                        \
            const size_t sa_ = (size_t)(bm + row_) * DM + kt_ + lch * 8;     \
            const size_t sb_ = (size_t)(bn + row_) * DM + kt_ + lch * 8;     \
            cpa16(base_ + G_AHI + d_, Ahi + sa_);                            \
            cpa16(base_ + G_ALO + d_, Alo + sa_);                            \
            cpa16(base_ + G_BHI + d_, Whi + sb_);                            \
            cpa16(base_ + G_BLO + d_, Wlo + sb_);                            \
        }                                                                    \
        cp_commit();                                                         \
    } while (0)

    G_ISSUE(0);
    cp_waitall();
    __syncthreads();

    for (int it = 0; it < 32; it++) {
        const uint32_t abase = sb + (it & 1) * G_STAGE;
        if (it < 31) G_ISSUE(it + 1);

#pragma unroll
        for (int kk = 0; kk < 2; kk++) {
            // byte offsets: k0 = kk*16 halves = kk*32 bytes
            const uint32_t acol = kk * 32 + (lane & 16);       // +16B if lane>=16
            const uint32_t arow = (lane & 15);
            unsigned ah[4][4], al[4][4];
#pragma unroll
            for (int i = 0; i < 4; i++) {
                const uint32_t ro = (uint32_t)(wm + 16 * i + arow) * 80 + acol;
                ldsm_x4(abase + G_AHI + ro, ah[i][0], ah[i][1], ah[i][2], ah[i][3]);
                ldsm_x4(abase + G_ALO + ro, al[i][0], al[i][1], al[i][2], al[i][3]);
            }
            const uint32_t brow = (lane & 7) + ((lane >> 4) << 3);
            const uint32_t bcol = kk * 32 + (lane & 8) * 2;
#pragma unroll
            for (int jp = 0; jp < 4; jp++) {
                const uint32_t ro = (uint32_t)(wn + 16 * jp + brow) * 80 + bcol;
                unsigned h0, h1, h2, h3, l0, l1, l2, l3;
                ldsm_x4(abase + G_BHI + ro, h0, h1, h2, h3);
                ldsm_x4(abase + G_BLO + ro, l0, l1, l2, l3);
#pragma unroll
                for (int i = 0; i < 4; i++) {
                    mma_f16(acc[i][2 * jp],     ah[i][0], ah[i][1], ah[i][2], ah[i][3], h0, h1);
                    mma_f16(acc[i][2 * jp],     ah[i][0], ah[i][1], ah[i][2], ah[i][3], l0, l1);
                    mma_f16(acc[i][2 * jp],     al[i][0], al[i][1], al[i][2], al[i][3], h0, h1);
                    mma_f16(acc[i][2 * jp + 1], ah[i][0], ah[i][1], ah[i][2], ah[i][3], h2, h3);
                    mma_f16(acc[i][2 * jp + 1], ah[i][0], ah[i][1], ah[i][2], ah[i][3], l2, l3);
                    mma_f16(acc[i][2 * jp + 1], al[i][0], al[i][1], al[i][2], al[i][3], h2, h3);
                }
            }
        }
        if (it < 31) { cp_waitall(); __syncthreads(); }
    }

    // Epilogue (validated R4 mapping): c0,c1 at (g, 2t,2t+1); c2,c3 at (g+8,..)
#pragma unroll
    for (int i = 0; i < 4; i++) {
#pragma unroll
        for (int j = 0; j < 8; j++) {
            const int n = bn + wn + 8 * j + 2 * t;
            const float b0 = bias[n];
            const float b1 = bias[n + 1];
#pragma unroll
            for (int half = 0; half < 2; half++) {
                const int m = bm + wm + 16 * i + g + half * 8;
                float2 val;
                val.x = acc[i][j][half * 2 + 0] + b0;
                val.y = acc[i][j][half * 2 + 1] + b1;
                if (MODE == 0) {
                    *reinterpret_cast<float2*>(out + (size_t)m * DM + n) = val;
                } else {
                    const int b  = m >> 11;
                    const int l  = m & (LQ - 1);
                    const int h  = n >> 6;
                    const int dd = n & (HD - 1);
                    *reinterpret_cast<float2*>(
                        out + (((size_t)(b * NH + h)) * LQ + l) * HD + dd) = val;
                }
            }
        }
    }
#undef G_ISSUE
}

// ---------------------------------------------------------------------------
// Flash attention: fp16 pre-split inputs, cp.async double-buffer, ldmatrix
// fragments, Q frags hoisted, P passed register-direct (C-frag == A-frag).
// One block = (b,h) x 64 Q rows; 4 warps x 16 rows; BK=32 per iter.
// Row stride 72 halves (144B, ldmatrix conflict-free).
// ---------------------------------------------------------------------------
#define F_QHI  0
#define F_QLO  9216
#define F_KHI  18432   // + st*4608
#define F_KLO  27648   // + st*4608
#define F_VH   36864   // + st*4608
#define F_MSK  46080   // + st*32
#define F_SMEM 46144

__global__ void __launch_bounds__(128)
flash_ldsm_kernel(const __half* __restrict__ qhi, const __half* __restrict__ qlo,
                  const __half* __restrict__ khi, const __half* __restrict__ klo,
                  const __half* __restrict__ vh,
                  const unsigned char* __restrict__ mask,
                  float* __restrict__ ctx)
{
    extern __shared__ __align__(128) char smem[];
    const int tid  = threadIdx.x;
    const int warp = tid >> 5;
    const int lane = tid & 31;
    const int g = lane >> 2;
    const int t = lane & 3;
    const int m0 = warp * 16;

    const int bh = blockIdx.y;
    const int b  = bh >> 4;
    const int h  = bh & 15;
    const int q0 = blockIdx.x * 64;
    const uint32_t sb = smem_u32(smem);

    const __half* qh_g = qhi + (((size_t)bh) * LQ + q0) * HD;
    const __half* ql_g = qlo + (((size_t)bh) * LQ + q0) * HD;
    const size_t kvbase = ((size_t)bh) * LK * HD;

    const int lrow = tid >> 3;   // 0..15
    const int lch  = tid & 7;    // 16B chunk in 128B row

    // K/V stage loader
#define F_ISSUE(IT)                                                          \
    do {                                                                     \
        const int kt_ = (IT) * 32;                                           \
        const uint32_t so_ = ((IT) & 1) * 4608;                              \
        _Pragma("unroll")                                                    \
        for (int p_ = 0; p_ < 2; p_++) {                                     \
            const int row_ = lrow + p_ * 16;                                 \
            const uint32_t d_ = row_ * 144 + lch * 16;                       \
            const size_t s_ = kvbase + (size_t)(kt_ + row_) * HD + lch * 8;  \
            cpa16(sb + F_KHI + so_ + d_, khi + s_);                          \
            cpa16(sb + F_KLO + so_ + d_, klo + s_);                          \
            cpa16(sb + F_VH  + so_ + d_, vh  + s_);                          \
        }                                                                    \
        if (tid < 2)                                                         \
            cpa16(sb + F_MSK + ((IT) & 1) * 32 + tid * 16,                   \
                  mask + (size_t)b * LK + kt_ + tid * 16);                   \
        cp_commit();                                                         \
    } while (0)

    // Prologue: Q tiles + stage 0
#pragma unroll
    for (int p = 0; p < 4; p++) {
        const int row = lrow + p * 16;
        const uint32_t d = row * 144 + lch * 16;
        cpa16(sb + F_QHI + d, qh_g + (size_t)row * HD + lch * 8);
        cpa16(sb + F_QLO + d, ql_g + (size_t)row * HD + lch * 8);
    }
    F_ISSUE(0);
    cp_waitall();
    __syncthreads();

    // Hoist Q fragments (A-frags for all 4 K=16 chunks)
    unsigned qh[4][4], ql[4][4];
    {
        const uint32_t qoff = (uint32_t)(m0 + (lane & 15)) * 144 + (lane & 16);
#pragma unroll
        for (int kk = 0; kk < 4; kk++) {
            ldsm_x4(sb + F_QHI + qoff + kk * 32,
                    qh[kk][0], qh[kk][1], qh[kk][2], qh[kk][3]);
            ldsm_x4(sb + F_QLO + qoff + kk * 32,
                    ql[kk][0], ql[kk][1], ql[kk][2], ql[kk][3]);
        }
    }

    float m_[2] = { -1e30f, -1e30f };
    float l_[2] = { 0.f, 0.f };
    float o[8][4];
#pragma unroll
    for (int n = 0; n < 8; n++)
#pragma unroll
        for (int c = 0; c < 4; c++) o[n][c] = 0.f;

    for (int it = 0; it < LK / 32; it++) {
        const uint32_t so = (it & 1) * 4608;
        if (it < LK / 32 - 1) F_ISSUE(it + 1);

        // S = Q*K^T (split-fp16)
        float s[4][4];
#pragma unroll
        for (int j = 0; j < 4; j++)
#pragma unroll
            for (int c = 0; c < 4; c++) s[j][c] = 0.f;

        const uint32_t krow = (lane & 7) + ((lane >> 4) << 3);
#pragma unroll
        for (int kk = 0; kk < 4; kk++) {
            const uint32_t kcol = kk * 32 + (lane & 8) * 2;
#pragma unroll
            for (int jp = 0; jp < 2; jp++) {
                const uint32_t ro = (uint32_t)(jp * 16 + krow) * 144 + kcol;
                unsigned h0, h1, h2, h3, l0, l1, l2, l3;
                ldsm_x4(sb + F_KHI + so + ro, h0, h1, h2, h3);
                ldsm_x4(sb + F_KLO + so + ro, l0, l1, l2, l3);
                mma_f16(s[2 * jp],     qh[kk][0], qh[kk][1], qh[kk][2], qh[kk][3], h0, h1);
                mma_f16(s[2 * jp],     qh[kk][0], qh[kk][1], qh[kk][2], qh[kk][3], l0, l1);
                mma_f16(s[2 * jp],     ql[kk][0], ql[kk][1], ql[kk][2], ql[kk][3], h0, h1);
                mma_f16(s[2 * jp + 1], qh[kk][0], qh[kk][1], qh[kk][2], qh[kk][3], h2, h3);
                mma_f16(s[2 * jp + 1], qh[kk][0], qh[kk][1], qh[kk][2], qh[kk][3], l2, l3);
                mma_f16(s[2 * jp + 1], ql[kk][0], ql[kk][1], ql[kk][2], ql[kk][3], h2, h3);
            }
        }

        // Mask
        const unsigned char* msk =
            reinterpret_cast<const unsigned char*>(smem) + F_MSK + (it & 1) * 32;
#pragma unroll
        for (int j = 0; j < 4; j++) {
            const int col = j * 8 + 2 * t;
            if (msk[col])     { s[j][0] = -1e30f; s[j][2] = -1e30f; }
            if (msk[col + 1]) { s[j][1] = -1e30f; s[j][3] = -1e30f; }
        }

        // Online softmax (validated)
        float r0 = fmaxf(fmaxf(s[0][0], s[0][1]), fmaxf(s[1][0], s[1][1]));
        r0 = fmaxf(r0, fmaxf(fmaxf(s[2][0], s[2][1]), fmaxf(s[3][0], s[3][1])));
        float r1 = fmaxf(fmaxf(s[0][2], s[0][3]), fmaxf(s[1][2], s[1][3]));
        r1 = fmaxf(r1, fmaxf(fmaxf(s[2][2], s[2][3]), fmaxf(s[3][2], s[3][3])));
        r0 = fmaxf(r0, __shfl_xor_sync(0xffffffffu, r0, 1));
        r0 = fmaxf(r0, __shfl_xor_sync(0xffffffffu, r0, 2));
        r1 = fmaxf(r1, __shfl_xor_sync(0xffffffffu, r1, 1));
        r1 = fmaxf(r1, __shfl_xor_sync(0xffffffffu, r1, 2));

        const float mn0 = fmaxf(m_[0], r0);
        const float mn1 = fmaxf(m_[1], r1);
        const float alpha0 = __expf(m_[0] - mn0);
        const float alpha1 = __expf(m_[1] - mn1);
        m_[0] = mn0; m_[1] = mn1;

        float sum0 = 0.f, sum1 = 0.f;
#pragma unroll
        for (int j = 0; j < 4; j++) {
            s[j][0] = __expf(s[j][0] - mn0);
            s[j][1] = __expf(s[j][1] - mn0);
            s[j][2] = __expf(s[j][2] - mn1);
            s[j][3] = __expf(s[j][3] - mn1);
            sum0 += s[j][0] + s[j][1];
            sum1 += s[j][2] + s[j][3];
        }
        sum0 += __shfl_xor_sync(0xffffffffu, sum0, 1);
        sum0 += __shfl_xor_sync(0xffffffffu, sum0, 2);
        sum1 += __shfl_xor_sync(0xffffffffu, sum1, 1);
        sum1 += __shfl_xor_sync(0xffffffffu, sum1, 2);
        l_[0] = l_[0] * alpha0 + sum0;
        l_[1] = l_[1] * alpha1 + sum1;

        // Rescale O
#pragma unroll
        for (int n = 0; n < 8; n++) {
            o[n][0] *= alpha0; o[n][1] *= alpha0;
            o[n][2] *= alpha1; o[n][3] *= alpha1;
        }

        // O += P*V. P A-frags come straight from s (C-frag == A-frag identity)
        const uint32_t vrow = (lane & 15);
        const uint32_t vcolb = (lane & 16);
#pragma unroll
        for (int kk = 0; kk < 2; kk++) {
            const unsigned a0 = pack_h2(__float2half_rn(s[2 * kk][0]),
                                        __float2half_rn(s[2 * kk][1]));
            const unsigned a1 = pack_h2(__float2half_rn(s[2 * kk][2]),
                                        __float2half_rn(s[2 * kk][3]));
            const unsigned a2 = pack_h2(__float2half_rn(s[2 * kk + 1][0]),
                                        __float2half_rn(s[2 * kk + 1][1]));
            const unsigned a3 = pack_h2(__float2half_rn(s[2 * kk + 1][2]),
                                        __float2half_rn(s[2 * kk + 1][3]));
            const uint32_t rbase = (uint32_t)(kk * 16 + vrow) * 144 + vcolb;
#pragma unroll
            for (int np = 0; np < 4; np++) {
                unsigned r0v, r1v, r2v, r3v;
                ldsm_x4_t(sb + F_VH + so + rbase + np * 32, r0v, r1v, r2v, r3v);
                mma_f16(o[2 * np],     a0, a1, a2, a3, r0v, r1v);
                mma_f16(o[2 * np + 1], a0, a1, a2, a3, r2v, r3v);
            }
        }

        if (it < LK / 32 - 1) { cp_waitall(); __syncthreads(); }
    }

    // Epilogue: normalize and write ctx[b, l, h*64 + d] (validated)
    const float inv0 = 1.f / l_[0];
    const float inv1 = 1.f / l_[1];
#pragma unroll
    for (int n = 0; n < 8; n++) {
        const int col = h * HD + n * 8 + 2 * t;
        const int row0 = q0 + m0 + g;
        float2 v0 = { o[n][0] * inv0, o[n][1] * inv0 };
        *reinterpret_cast<float2*>(
            ctx + ((size_t)b * LQ + row0) * DM + col) = v0;
        float2 v1 = { o[n][2] * inv1, o[n][3] * inv1 };
        *reinterpret_cast<float2*>(
            ctx + ((size_t)b * LQ + row0 + 8) * DM + col) = v1;
    }
#undef F_ISSUE
}

// ---------------------------------------------------------------------------
// Launch
// ---------------------------------------------------------------------------
extern "C" void kernel_launch(void* const* d_in, const int* in_sizes, int n_in,
                              void* d_out, int out_size)
{
    const float* query = (const float*)d_in[0];
    const float* key   = (const float*)d_in[1];
    const float* value = (const float*)d_in[2];
    const float* cos_q = (const float*)d_in[3];
    const float* sin_q = (const float*)d_in[4];
    const float* cos_k = (const float*)d_in[5];
    const float* sin_k = (const float*)d_in[6];
    const unsigned char* mask = (const unsigned char*)d_in[7];
    const float* Wq = (const float*)d_in[8];
    const float* bq = (const float*)d_in[9];
    const float* Wk = (const float*)d_in[10];
    const float* bk = (const float*)d_in[11];
    const float* Wv = (const float*)d_in[12];
    const float* bv = (const float*)d_in[13];
    const float* Wo = (const float*)d_in[14];
    const float* bo = (const float*)d_in[15];
    float* out = (float*)d_out;

    float *pq, *pk, *pv, *pctx;
    __half *pahi, *palo, *pwhi, *pwlo;
    __half *pqhi, *pqlo, *pkhi, *pklo, *pvh;
    cudaGetSymbolAddress((void**)&pq,   g_q);
    cudaGetSymbolAddress((void**)&pk,   g_k);
    cudaGetSymbolAddress((void**)&pv,   g_v);
    cudaGetSymbolAddress((void**)&pctx, g_ctx);
    cudaGetSymbolAddress((void**)&pahi, g_ahi);
    cudaGetSymbolAddress((void**)&palo, g_alo);
    cudaGetSymbolAddress((void**)&pwhi, g_whi);
    cudaGetSymbolAddress((void**)&pwlo, g_wlo);
    cudaGetSymbolAddress((void**)&pqhi, g_qhi);
    cudaGetSymbolAddress((void**)&pqlo, g_qlo);
    cudaGetSymbolAddress((void**)&pkhi, g_khi);
    cudaGetSymbolAddress((void**)&pklo, g_klo);
    cudaGetSymbolAddress((void**)&pvh,  g_vh);

    cudaFuncSetAttribute(gemm_cp_kernel<0>,
                         cudaFuncAttributeMaxDynamicSharedMemorySize, G_SMEM);
    cudaFuncSetAttribute(gemm_cp_kernel<1>,
                         cudaFuncAttributeMaxDynamicSharedMemorySize, G_SMEM);

    const int nA4 = MTOT * DM / 4;
    const int nW4 = DM * DM / 4;
    dim3 gg(DM / 128, MTOT / 128);   // (8, 64)

    // Q projection
    split_kernel<<<(nA4 + 255) / 256, 256>>>((const float4*)query,
                                             (uint2*)pahi, (uint2*)palo, nA4);
    split_kernel<<<(nW4 + 255) / 256, 256>>>((const float4*)Wq,
                                             (uint2*)pwhi, (uint2*)pwlo, nW4);
    gemm_cp_kernel<1><<<gg, 128, G_SMEM>>>(pahi, palo, pwhi, pwlo, bq, pq);

    // K projection
    split_kernel<<<(nA4 + 255) / 256, 256>>>((const float4*)key,
                                             (uint2*)pahi, (uint2*)palo, nA4);
    split_kernel<<<(nW4 + 255) / 256, 256>>>((const float4*)Wk,
                                             (uint2*)pwhi, (uint2*)pwlo, nW4);
    gemm_cp_kernel<1><<<gg, 128, G_SMEM>>>(pahi, palo, pwhi, pwlo, bk, pk);

    // V projection
    split_kernel<<<(nA4 + 255) / 256, 256>>>((const float4*)value,
                                             (uint2*)pahi, (uint2*)palo, nA4);
    split_kernel<<<(nW4 + 255) / 256, 256>>>((const float4*)Wv,
                                             (uint2*)pwhi, (uint2*)pwlo, nW4);
    gemm_cp_kernel<1><<<gg, 128, G_SMEM>>>(pahi, palo, pwhi, pwlo, bv, pv);

    // RoPE + split to fp16 (Q scale 1/8 folded), V convert
    const int rope_total = BB * NH * LQ * 32;
    rope_split_kernel<<<(rope_total + 255) / 256, 256>>>(pq, cos_q, sin_q,
                                                         pqhi, pqlo, 0.125f);
    rope_split_kernel<<<(rope_total + 255) / 256, 256>>>(pk, cos_k, sin_k,
                                                         pkhi, pklo, 1.0f);
    vconv_kernel<<<(nA4 + 255) / 256, 256>>>((const float4*)pv, (uint2*)pvh, nA4);

    // Attention
    flash_ldsm_kernel<<<dim3(LQ / 64, BB * NH), 128, F_SMEM>>>(
        pqhi, pqlo, pkhi, pklo, pvh, mask, pctx);

    // Output projection
    split_kernel<<<(nA4 + 255) / 256, 256>>>((const float4*)pctx,
                                             (uint2*)pahi, (uint2*)palo, nA4);
    split_kernel<<<(nW4 + 255) / 256, 256>>>((const float4*)Wo,
                                             (uint2*)pwhi, (uint2*)pwlo, nW4);
    gemm_cp_kernel<0><<<gg, 128, G_SMEM>>>(pahi, palo, pwhi, pwlo, bo, out);
}

// round 8
// speedup vs baseline: 3.7890x; 1.0221x over previous
#include <cuda_runtime.h>
#include <cuda_fp16.h>
#include <math.h>
#include <stdint.h>

// Problem constants
#define BB   4
#define NH   16
#define HD   64
#define DM   1024
#define LQ   2048
#define LK   2048
#define MTOT (BB * LQ)

// ---------------------------------------------------------------------------
// Scratch (device globals — no allocation allowed)
// ---------------------------------------------------------------------------
__device__ __half g_ahi[MTOT * DM];
__device__ __half g_alo[MTOT * DM];
__device__ __half g_whi[DM * DM];
__device__ __half g_wlo[DM * DM];
__device__ __half g_qhi[BB * NH * LQ * HD];
__device__ __half g_qlo[BB * NH * LQ * HD];
__device__ __half g_khi[BB * NH * LK * HD];
__device__ __half g_klo[BB * NH * LK * HD];
__device__ __half g_vh [BB * NH * LK * HD];
__device__ __half g_chi[MTOT * DM];
__device__ __half g_clo[MTOT * DM];

// ---------------------------------------------------------------------------
// Helpers
// ---------------------------------------------------------------------------
__device__ __forceinline__ unsigned pack_h2(__half a, __half b) {
    return (unsigned)__half_as_ushort(a) | ((unsigned)__half_as_ushort(b) << 16);
}

__device__ __forceinline__ void split2(float x, float y,
                                       unsigned& hi, unsigned& lo) {
    __half hx = __float2half_rn(x);
    __half hy = __float2half_rn(y);
    __half lx = __float2half_rn(x - __half2float(hx));
    __half ly = __float2half_rn(y - __half2float(hy));
    hi = pack_h2(hx, hy);
    lo = pack_h2(lx, ly);
}

__device__ __forceinline__ float ex2f(float x) {
    float y;
    asm("ex2.approx.ftz.f32 %0, %1;" : "=f"(y) : "f"(x));
    return y;
}

__device__ __forceinline__ void mma_f16(float c[4],
                                        unsigned a0, unsigned a1,
                                        unsigned a2, unsigned a3,
                                        unsigned b0, unsigned b1) {
    asm volatile(
        "mma.sync.aligned.m16n8k16.row.col.f32.f16.f16.f32 "
        "{%0,%1,%2,%3}, {%4,%5,%6,%7}, {%8,%9}, {%0,%1,%2,%3};"
        : "+f"(c[0]), "+f"(c[1]), "+f"(c[2]), "+f"(c[3])
        : "r"(a0), "r"(a1), "r"(a2), "r"(a3), "r"(b0), "r"(b1));
}

__device__ __forceinline__ uint32_t smem_u32(const void* p) {
    uint32_t a;
    asm("{ .reg .u64 t; cvta.to.shared.u64 t, %1; cvt.u32.u64 %0, t; }"
        : "=r"(a) : "l"(p));
    return a;
}

__device__ __forceinline__ void ldsm_x4(uint32_t addr, unsigned& r0,
                                        unsigned& r1, unsigned& r2,
                                        unsigned& r3) {
    asm volatile(
        "ldmatrix.sync.aligned.m8n8.x4.shared.b16 {%0,%1,%2,%3}, [%4];"
        : "=r"(r0), "=r"(r1), "=r"(r2), "=r"(r3) : "r"(addr));
}

__device__ __forceinline__ void ldsm_x4_t(uint32_t addr, unsigned& r0,
                                          unsigned& r1, unsigned& r2,
                                          unsigned& r3) {
    asm volatile(
        "ldmatrix.sync.aligned.m8n8.x4.trans.shared.b16 {%0,%1,%2,%3}, [%4];"
        : "=r"(r0), "=r"(r1), "=r"(r2), "=r"(r3) : "r"(addr));
}

__device__ __forceinline__ void cpa16(uint32_t dst, const void* src) {
    asm volatile("cp.async.cg.shared.global [%0], [%1], 16;"
                 :: "r"(dst), "l"(src) : "memory");
}
__device__ __forceinline__ void cp_commit() {
    asm volatile("cp.async.commit_group;" ::: "memory");
}
__device__ __forceinline__ void cp_waitall() {
    asm volatile("cp.async.wait_group 0;" ::: "memory");
}

#define QSCALE 0.18033688011112042f   /* 0.125 * log2(e) */

// ---------------------------------------------------------------------------
// Pre-split kernel (inputs and weights)
// ---------------------------------------------------------------------------
__global__ void split_kernel(const float4* __restrict__ src,
                             uint2* __restrict__ hi,
                             uint2* __restrict__ lo, int n4)
{
    int i = blockIdx.x * blockDim.x + threadIdx.x;
    if (i >= n4) return;
    float4 v = src[i];
    unsigned h0, l0, h1, l1;
    split2(v.x, v.y, h0, l0);
    split2(v.z, v.w, h1, l1);
    hi[i] = make_uint2(h0, h1);
    lo[i] = make_uint2(l0, l1);
}

// ---------------------------------------------------------------------------
// Split-fp16 GEMM (cp.async double-buffer + ldmatrix), 128x128 tile, 4 warps.
// MODE 0: C fp32 [m][n] (out projection)
// MODE 2: RoPE fused + split -> (ohi, olo) in [b,h,l,d] layout (Q/K proj)
// MODE 3: plain fp16 -> ohi in [b,h,l,d] layout (V proj)
// ---------------------------------------------------------------------------
#define G_STAGE 40960
#define G_AHI   0
#define G_ALO   10240
#define G_BHI   20480
#define G_BLO   30720
#define G_SMEM  (2 * G_STAGE)

template <int MODE>
__global__ void __launch_bounds__(128)
gemm_cp_kernel(const __half* __restrict__ Ahi, const __half* __restrict__ Alo,
               const __half* __restrict__ Whi, const __half* __restrict__ Wlo,
               const float* __restrict__ bias,
               const float* __restrict__ cosb, const float* __restrict__ sinb,
               float scale, float* __restrict__ outf,
               __half* __restrict__ ohi, __half* __restrict__ olo)
{
    extern __shared__ __align__(128) char smem[];
    const int tid  = threadIdx.x;
    const int warp = tid >> 5;
    const int lane = tid & 31;
    const int g = lane >> 2;
    const int t = lane & 3;
    const int wm = (warp & 1) * 64;
    const int wn = (warp >> 1) * 64;
    const int bm = blockIdx.y * 128;
    const int bn = blockIdx.x * 128;
    const uint32_t sb = smem_u32(smem);

    float acc[4][8][4];
#pragma unroll
    for (int i = 0; i < 4; i++)
#pragma unroll
        for (int j = 0; j < 8; j++)
#pragma unroll
            for (int c = 0; c < 4; c++) acc[i][j][c] = 0.f;

    const int lrow = tid >> 2;
    const int lch  = tid & 3;
#define G_ISSUE(IT)                                                          \
    do {                                                                     \
        const int kt_ = (IT) * 32;                                           \
        const uint32_t base_ = sb + ((IT) & 1) * G_STAGE;                    \
        _Pragma("unroll")                                                    \
        for (int p_ = 0; p_ < 4; p_++) {                                     \
            const int row_ = lrow + p_ * 32;                                 \
            const uint32_t d_ = row_ * 80 + lch * 16;                        \
            const size_t sa_ = (size_t)(bm + row_) * DM + kt_ + lch * 8;     \
            const size_t sb_ = (size_t)(bn + row_) * DM + kt_ + lch * 8;     \
            cpa16(base_ + G_AHI + d_, Ahi + sa_);                            \
            cpa16(base_ + G_ALO + d_, Alo + sa_);                            \
            cpa16(base_ + G_BHI + d_, Whi + sb_);                            \
            cpa16(base_ + G_BLO + d_, Wlo + sb_);                            \
        }                                                                    \
        cp_commit();                                                         \
    } while (0)

    G_ISSUE(0);
    cp_waitall();
    __syncthreads();

    for (int it = 0; it < 32; it++) {
        const uint32_t abase = sb + (it & 1) * G_STAGE;
        if (it < 31) G_ISSUE(it + 1);

#pragma unroll
        for (int kk = 0; kk < 2; kk++) {
            const uint32_t acol = kk * 32 + (lane & 16);
            const uint32_t arow = (lane & 15);
            unsigned ah[4][4], al[4][4];
#pragma unroll
            for (int i = 0; i < 4; i++) {
                const uint32_t ro = (uint32_t)(wm + 16 * i + arow) * 80 + acol;
                ldsm_x4(abase + G_AHI + ro, ah[i][0], ah[i][1], ah[i][2], ah[i][3]);
                ldsm_x4(abase + G_ALO + ro, al[i][0], al[i][1], al[i][2], al[i][3]);
            }
            const uint32_t brow = (lane & 7) + ((lane >> 4) << 3);
            const uint32_t bcol = kk * 32 + (lane & 8) * 2;
#pragma unroll
            for (int jp = 0; jp < 4; jp++) {
                const uint32_t ro = (uint32_t)(wn + 16 * jp + brow) * 80 + bcol;
                unsigned h0, h1, h2, h3, l0, l1, l2, l3;
                ldsm_x4(abase + G_BHI + ro, h0, h1, h2, h3);
                ldsm_x4(abase + G_BLO + ro, l0, l1, l2, l3);
#pragma unroll
                for (int i = 0; i < 4; i++) {
                    mma_f16(acc[i][2 * jp],     ah[i][0], ah[i][1], ah[i][2], ah[i][3], h0, h1);
                    mma_f16(acc[i][2 * jp],     ah[i][0], ah[i][1], ah[i][2], ah[i][3], l0, l1);
                    mma_f16(acc[i][2 * jp],     al[i][0], al[i][1], al[i][2], al[i][3], h0, h1);
                    mma_f16(acc[i][2 * jp + 1], ah[i][0], ah[i][1], ah[i][2], ah[i][3], h2, h3);
                    mma_f16(acc[i][2 * jp + 1], ah[i][0], ah[i][1], ah[i][2], ah[i][3], l2, l3);
                    mma_f16(acc[i][2 * jp + 1], al[i][0], al[i][1], al[i][2], al[i][3], h2, h3);
                }
            }
        }
        if (it < 31) { cp_waitall(); __syncthreads(); }
    }

    // ---- Epilogues ----
    const int h  = (bn + wn) >> 6;    // head for this warp's N-tile (N=64 = 1 head)

    if (MODE == 0) {
#pragma unroll
        for (int i = 0; i < 4; i++) {
#pragma unroll
            for (int j = 0; j < 8; j++) {
                const int n = bn + wn + 8 * j + 2 * t;
                const float b0 = bias[n];
                const float b1 = bias[n + 1];
#pragma unroll
                for (int half = 0; half < 2; half++) {
                    const int m = bm + wm + 16 * i + g + half * 8;
                    float2 val;
                    val.x = acc[i][j][half * 2 + 0] + b0;
                    val.y = acc[i][j][half * 2 + 1] + b1;
                    *reinterpret_cast<float2*>(outf + (size_t)m * DM + n) = val;
                }
            }
        }
    } else if (MODE == 2) {
        // RoPE + split. Pair: col dd (j<4) with col dd+32 (j+4).
#pragma unroll
        for (int i = 0; i < 4; i++) {
#pragma unroll
            for (int half = 0; half < 2; half++) {
                const int m = bm + wm + 16 * i + g + half * 8;
                const int b = m >> 11;
                const int l = m & (LQ - 1);
                const size_t rowoff = (((size_t)(b * NH + h)) * LQ + l) * HD;
                const float* cr = cosb + ((size_t)b * LQ + l) * HD;
                const float* sr = sinb + ((size_t)b * LQ + l) * HD;
#pragma unroll
                for (int j = 0; j < 4; j++) {
                    const int dd = 8 * j + 2 * t;
                    const int n1 = bn + wn + dd;
                    float x1a = acc[i][j][half * 2 + 0] + bias[n1];
                    float x1b = acc[i][j][half * 2 + 1] + bias[n1 + 1];
                    float x2a = acc[i][j + 4][half * 2 + 0] + bias[n1 + 32];
                    float x2b = acc[i][j + 4][half * 2 + 1] + bias[n1 + 33];
                    float y1a = (x1a * cr[dd]      - x2a * sr[dd])      * scale;
                    float y1b = (x1b * cr[dd + 1]  - x2b * sr[dd + 1])  * scale;
                    float y2a = (x2a * cr[dd + 32] + x1a * sr[dd + 32]) * scale;
                    float y2b = (x2b * cr[dd + 33] + x1b * sr[dd + 33]) * scale;
                    unsigned h1, l1, h2, l2;
                    split2(y1a, y1b, h1, l1);
                    split2(y2a, y2b, h2, l2);
                    *reinterpret_cast<unsigned*>(ohi + rowoff + dd)      = h1;
                    *reinterpret_cast<unsigned*>(olo + rowoff + dd)      = l1;
                    *reinterpret_cast<unsigned*>(ohi + rowoff + dd + 32) = h2;
                    *reinterpret_cast<unsigned*>(olo + rowoff + dd + 32) = l2;
                }
            }
        }
    } else {  // MODE 3: plain fp16 head layout (V)
#pragma unroll
        for (int i = 0; i < 4; i++) {
#pragma unroll
            for (int half = 0; half < 2; half++) {
                const int m = bm + wm + 16 * i + g + half * 8;
                const int b = m >> 11;
                const int l = m & (LQ - 1);
                const size_t rowoff = (((size_t)(b * NH + h)) * LQ + l) * HD;
#pragma unroll
                for (int j = 0; j < 8; j++) {
                    const int dd = 8 * j + 2 * t;
                    const int n = bn + wn + dd;
                    float vx = acc[i][j][half * 2 + 0] + bias[n];
                    float vy = acc[i][j][half * 2 + 1] + bias[n + 1];
                    *reinterpret_cast<unsigned*>(ohi + rowoff + dd) =
                        pack_h2(__float2half_rn(vx), __float2half_rn(vy));
                }
            }
        }
    }
#undef G_ISSUE
}

// ---------------------------------------------------------------------------
// Flash attention, BK=64: fp16 pre-split inputs, cp.async double-buffer,
// ldmatrix fragments, Q hoisted, P register-direct, ex2-based softmax
// (log2e folded into Q scale). Writes split ctx (hi/lo fp16) directly.
// One block = (b,h) x 64 Q rows; 4 warps x 16 rows; 32 iters of 64 keys.
// ---------------------------------------------------------------------------
#define F_STG   27776
#define F_QHI   0
#define F_QLO   9216
#define F_KHI(s) (18432 + (s) * F_STG)
#define F_KLO(s) (F_KHI(s) + 9216)
#define F_VH(s)  (F_KHI(s) + 18432)
#define F_MSK(s) (F_KHI(s) + 27648)
#define F_SMEM  (18432 + 2 * F_STG)

__global__ void __launch_bounds__(128)
flash_bk64_kernel(const __half* __restrict__ qhi, const __half* __restrict__ qlo,
                  const __half* __restrict__ khi, const __half* __restrict__ klo,
                  const __half* __restrict__ vh,
                  const unsigned char* __restrict__ mask,
                  __half* __restrict__ chi, __half* __restrict__ clo)
{
    extern __shared__ __align__(128) char smem[];
    const int tid  = threadIdx.x;
    const int warp = tid >> 5;
    const int lane = tid & 31;
    const int g = lane >> 2;
    const int t = lane & 3;
    const int m0 = warp * 16;

    const int bh = blockIdx.y;
    const int b  = bh >> 4;
    const int h  = bh & 15;
    const int q0 = blockIdx.x * 64;
    const uint32_t sb = smem_u32(smem);

    const __half* qh_g = qhi + (((size_t)bh) * LQ + q0) * HD;
    const __half* ql_g = qlo + (((size_t)bh) * LQ + q0) * HD;
    const size_t kvbase = ((size_t)bh) * LK * HD;

    const int lrow = tid >> 3;   // 0..15
    const int lch  = tid & 7;

#define F_ISSUE(IT)                                                          \
    do {                                                                     \
        const int kt_ = (IT) * 64;                                           \
        const int st_ = (IT) & 1;                                            \
        _Pragma("unroll")                                                    \
        for (int p_ = 0; p_ < 4; p_++) {                                     \
            const int row_ = lrow + p_ * 16;                                 \
            const uint32_t d_ = row_ * 144 + lch * 16;                       \
            const size_t s_ = kvbase + (size_t)(kt_ + row_) * HD + lch * 8;  \
            cpa16(sb + F_KHI(st_) + d_, khi + s_);                           \
            cpa16(sb + F_KLO(st_) + d_, klo + s_);                           \
            cpa16(sb + F_VH(st_)  + d_, vh  + s_);                           \
        }                                                                    \
        if (tid < 4)                                                         \
            cpa16(sb + F_MSK(st_) + tid * 16,                                \
                  mask + (size_t)b * LK + kt_ + tid * 16);                   \
        cp_commit();                                                         \
    } while (0)

    // Prologue: Q tiles + stage 0
#pragma unroll
    for (int p = 0; p < 4; p++) {
        const int row = lrow + p * 16;
        const uint32_t d = row * 144 + lch * 16;
        cpa16(sb + F_QHI + d, qh_g + (size_t)row * HD + lch * 8);
        cpa16(sb + F_QLO + d, ql_g + (size_t)row * HD + lch * 8);
    }
    F_ISSUE(0);
    cp_waitall();
    __syncthreads();

    unsigned qh[4][4], ql[4][4];
    {
        const uint32_t qoff = (uint32_t)(m0 + (lane & 15)) * 144 + (lane & 16);
#pragma unroll
        for (int kk = 0; kk < 4; kk++) {
            ldsm_x4(sb + F_QHI + qoff + kk * 32,
                    qh[kk][0], qh[kk][1], qh[kk][2], qh[kk][3]);
            ldsm_x4(sb + F_QLO + qoff + kk * 32,
                    ql[kk][0], ql[kk][1], ql[kk][2], ql[kk][3]);
        }
    }

    float m_[2] = { -1e30f, -1e30f };
    float l_[2] = { 0.f, 0.f };
    float o[8][4];
#pragma unroll
    for (int n = 0; n < 8; n++)
#pragma unroll
        for (int c = 0; c < 4; c++) o[n][c] = 0.f;

    for (int it = 0; it < LK / 64; it++) {
        const int st = it & 1;
        if (it < LK / 64 - 1) F_ISSUE(it + 1);

        // S = Q*K^T (split-fp16), 64 keys
        float s[8][4];
#pragma unroll
        for (int j = 0; j < 8; j++)
#pragma unroll
            for (int c = 0; c < 4; c++) s[j][c] = 0.f;

        const uint32_t krow = (lane & 7) + ((lane >> 4) << 3);
#pragma unroll
        for (int kk = 0; kk < 4; kk++) {
            const uint32_t kcol = kk * 32 + (lane & 8) * 2;
#pragma unroll
            for (int jp = 0; jp < 4; jp++) {
                const uint32_t ro = (uint32_t)(jp * 16 + krow) * 144 + kcol;
                unsigned h0, h1, h2, h3, l0, l1, l2, l3;
                ldsm_x4(sb + F_KHI(st) + ro, h0, h1, h2, h3);
                ldsm_x4(sb + F_KLO(st) + ro, l0, l1, l2, l3);
                mma_f16(s[2 * jp],     qh[kk][0], qh[kk][1], qh[kk][2], qh[kk][3], h0, h1);
                mma_f16(s[2 * jp],     qh[kk][0], qh[kk][1], qh[kk][2], qh[kk][3], l0, l1);
                mma_f16(s[2 * jp],     ql[kk][0], ql[kk][1], ql[kk][2], ql[kk][3], h0, h1);
                mma_f16(s[2 * jp + 1], qh[kk][0], qh[kk][1], qh[kk][2], qh[kk][3], h2, h3);
                mma_f16(s[2 * jp + 1], qh[kk][0], qh[kk][1], qh[kk][2], qh[kk][3], l2, l3);
                mma_f16(s[2 * jp + 1], ql[kk][0], ql[kk][1], ql[kk][2], ql[kk][3], h2, h3);
            }
        }

        // Mask (additive -inf in log2 domain works the same)
        const unsigned char* msk =
            reinterpret_cast<const unsigned char*>(smem) + F_MSK(st);
#pragma unroll
        for (int j = 0; j < 8; j++) {
            const int col = j * 8 + 2 * t;
            if (msk[col])     { s[j][0] = -1e30f; s[j][2] = -1e30f; }
            if (msk[col + 1]) { s[j][1] = -1e30f; s[j][3] = -1e30f; }
        }

        // Online softmax in base-2 domain
        float r0 = -1e30f, r1 = -1e30f;
#pragma unroll
        for (int j = 0; j < 8; j++) {
            r0 = fmaxf(r0, fmaxf(s[j][0], s[j][1]));
            r1 = fmaxf(r1, fmaxf(s[j][2], s[j][3]));
        }
        r0 = fmaxf(r0, __shfl_xor_sync(0xffffffffu, r0, 1));
        r0 = fmaxf(r0, __shfl_xor_sync(0xffffffffu, r0, 2));
        r1 = fmaxf(r1, __shfl_xor_sync(0xffffffffu, r1, 1));
        r1 = fmaxf(r1, __shfl_xor_sync(0xffffffffu, r1, 2));

        const float mn0 = fmaxf(m_[0], r0);
        const float mn1 = fmaxf(m_[1], r1);
        const float alpha0 = ex2f(m_[0] - mn0);
        const float alpha1 = ex2f(m_[1] - mn1);
        m_[0] = mn0; m_[1] = mn1;

        float sum0 = 0.f, sum1 = 0.f;
#pragma unroll
        for (int j = 0; j < 8; j++) {
            s[j][0] = ex2f(s[j][0] - mn0);
            s[j][1] = ex2f(s[j][1] - mn0);
            s[j][2] = ex2f(s[j][2] - mn1);
            s[j][3] = ex2f(s[j][3] - mn1);
            sum0 += s[j][0] + s[j][1];
            sum1 += s[j][2] + s[j][3];
        }
        sum0 += __shfl_xor_sync(0xffffffffu, sum0, 1);
        sum0 += __shfl_xor_sync(0xffffffffu, sum0, 2);
        sum1 += __shfl_xor_sync(0xffffffffu, sum1, 1);
        sum1 += __shfl_xor_sync(0xffffffffu, sum1, 2);
        l_[0] = l_[0] * alpha0 + sum0;
        l_[1] = l_[1] * alpha1 + sum1;

#pragma unroll
        for (int n = 0; n < 8; n++) {
            o[n][0] *= alpha0; o[n][1] *= alpha0;
            o[n][2] *= alpha1; o[n][3] *= alpha1;
        }

        // O += P*V (64 keys = 4 K=16 chunks); P from s register-direct
        const uint32_t vrow = (lane & 15);
        const uint32_t vcolb = (lane & 16);
#pragma unroll
        for (int kk = 0; kk < 4; kk++) {
            const unsigned a0 = pack_h2(__float2half_rn(s[2 * kk][0]),
                                        __float2half_rn(s[2 * kk][1]));
            const unsigned a1 = pack_h2(__float2half_rn(s[2 * kk][2]),
                                        __float2half_rn(s[2 * kk][3]));
            const unsigned a2 = pack_h2(__float2half_rn(s[2 * kk + 1][0]),
                                        __float2half_rn(s[2 * kk + 1][1]));
            const unsigned a3 = pack_h2(__float2half_rn(s[2 * kk + 1][2]),
                                        __float2half_rn(s[2 * kk + 1][3]));
            const uint32_t rbase = (uint32_t)(kk * 16 + vrow) * 144 + vcolb;
#pragma unroll
            for (int np = 0; np < 4; np++) {
                unsigned r0v, r1v, r2v, r3v;
                ldsm_x4_t(sb + F_VH(st) + rbase + np * 32, r0v, r1v, r2v, r3v);
                mma_f16(o[2 * np],     a0, a1, a2, a3, r0v, r1v);
                mma_f16(o[2 * np + 1], a0, a1, a2, a3, r2v, r3v);
            }
        }

        if (it < LK / 64 - 1) { cp_waitall(); __syncthreads(); }
    }

    // Epilogue: normalize, split, write ctx hi/lo at [b, l, h*64 + d]
    const float inv0 = 1.f / l_[0];
    const float inv1 = 1.f / l_[1];
#pragma unroll
    for (int n = 0; n < 8; n++) {
        const int col = h * HD + n * 8 + 2 * t;
        const int row0 = q0 + m0 + g;
        const size_t off0 = ((size_t)b * LQ + row0) * DM + col;
        const size_t off1 = ((size_t)b * LQ + row0 + 8) * DM + col;
        unsigned hi0, lo0, hi1, lo1;
        split2(o[n][0] * inv0, o[n][1] * inv0, hi0, lo0);
        split2(o[n][2] * inv1, o[n][3] * inv1, hi1, lo1);
        *reinterpret_cast<unsigned*>(chi + off0) = hi0;
        *reinterpret_cast<unsigned*>(clo + off0) = lo0;
        *reinterpret_cast<unsigned*>(chi + off1) = hi1;
        *reinterpret_cast<unsigned*>(clo + off1) = lo1;
    }
#undef F_ISSUE
}

// ---------------------------------------------------------------------------
// Launch
// ---------------------------------------------------------------------------
extern "C" void kernel_launch(void* const* d_in, const int* in_sizes, int n_in,
                              void* d_out, int out_size)
{
    const float* query = (const float*)d_in[0];
    const float* key   = (const float*)d_in[1];
    const float* value = (const float*)d_in[2];
    const float* cos_q = (const float*)d_in[3];
    const float* sin_q = (const float*)d_in[4];
    const float* cos_k = (const float*)d_in[5];
    const float* sin_k = (const float*)d_in[6];
    const unsigned char* mask = (const unsigned char*)d_in[7];
    const float* Wq = (const float*)d_in[8];
    const float* bq = (const float*)d_in[9];
    const float* Wk = (const float*)d_in[10];
    const float* bk = (const float*)d_in[11];
    const float* Wv = (const float*)d_in[12];
    const float* bv = (const float*)d_in[13];
    const float* Wo = (const float*)d_in[14];
    const float* bo = (const float*)d_in[15];
    float* out = (float*)d_out;

    __half *pahi, *palo, *pwhi, *pwlo;
    __half *pqhi, *pqlo, *pkhi, *pklo, *pvh, *pchi, *pclo;
    cudaGetSymbolAddress((void**)&pahi, g_ahi);
    cudaGetSymbolAddress((void**)&palo, g_alo);
    cudaGetSymbolAddress((void**)&pwhi, g_whi);
    cudaGetSymbolAddress((void**)&pwlo, g_wlo);
    cudaGetSymbolAddress((void**)&pqhi, g_qhi);
    cudaGetSymbolAddress((void**)&pqlo, g_qlo);
    cudaGetSymbolAddress((void**)&pkhi, g_khi);
    cudaGetSymbolAddress((void**)&pklo, g_klo);
    cudaGetSymbolAddress((void**)&pvh,  g_vh);
    cudaGetSymbolAddress((void**)&pchi, g_chi);
    cudaGetSymbolAddress((void**)&pclo, g_clo);

    cudaFuncSetAttribute(gemm_cp_kernel<0>,
                         cudaFuncAttributeMaxDynamicSharedMemorySize, G_SMEM);
    cudaFuncSetAttribute(gemm_cp_kernel<2>,
                         cudaFuncAttributeMaxDynamicSharedMemorySize, G_SMEM);
    cudaFuncSetAttribute(gemm_cp_kernel<3>,
                         cudaFuncAttributeMaxDynamicSharedMemorySize, G_SMEM);
    cudaFuncSetAttribute(flash_bk64_kernel,
                         cudaFuncAttributeMaxDynamicSharedMemorySize, F_SMEM);

    const int nA4 = MTOT * DM / 4;
    const int nW4 = DM * DM / 4;
    dim3 gg(DM / 128, MTOT / 128);   // (8, 64)

    // Q projection (+RoPE, scale = 0.125*log2e folded)
    split_kernel<<<(nA4 + 255) / 256, 256>>>((const float4*)query,
                                             (uint2*)pahi, (uint2*)palo, nA4);
    split_kernel<<<(nW4 + 255) / 256, 256>>>((const float4*)Wq,
                                             (uint2*)pwhi, (uint2*)pwlo, nW4);
    gemm_cp_kernel<2><<<gg, 128, G_SMEM>>>(pahi, palo, pwhi, pwlo, bq,
                                           cos_q, sin_q, QSCALE,
                                           nullptr, pqhi, pqlo);

    // K projection (+RoPE, scale 1)
    split_kernel<<<(nA4 + 255) / 256, 256>>>((const float4*)key,
                                             (uint2*)pahi, (uint2*)palo, nA4);
    split_kernel<<<(nW4 + 255) / 256, 256>>>((const float4*)Wk,
                                             (uint2*)pwhi, (uint2*)pwlo, nW4);
    gemm_cp_kernel<2><<<gg, 128, G_SMEM>>>(pahi, palo, pwhi, pwlo, bk,
                                           cos_k, sin_k, 1.0f,
                                           nullptr, pkhi, pklo);

    // V projection (fp16 direct)
    split_kernel<<<(nA4 + 255) / 256, 256>>>((const float4*)value,
                                             (uint2*)pahi, (uint2*)palo, nA4);
    split_kernel<<<(nW4 + 255) / 256, 256>>>((const float4*)Wv,
                                             (uint2*)pwhi, (uint2*)pwlo, nW4);
    gemm_cp_kernel<3><<<gg, 128, G_SMEM>>>(pahi, palo, pwhi, pwlo, bv,
                                           nullptr, nullptr, 1.0f,
                                           nullptr, pvh, nullptr);

    // Attention (writes split ctx)
    flash_bk64_kernel<<<dim3(LQ / 64, BB * NH), 128, F_SMEM>>>(
        pqhi, pqlo, pkhi, pklo, pvh, mask, pchi, pclo);

    // Output projection (A = split ctx)
    split_kernel<<<(nW4 + 255) / 256, 256>>>((const float4*)Wo,
                                             (uint2*)pwhi, (uint2*)pwlo, nW4);
    gemm_cp_kernel<0><<<gg, 128, G_SMEM>>>(pchi, pclo, pwhi, pwlo, bo,
                                           nullptr, nullptr, 1.0f,
                                           out, nullptr, nullptr);
}

// round 9
// speedup vs baseline: 3.8871x; 1.0259x over previous
#include <cuda_runtime.h>
#include <cuda_fp16.h>
#include <math.h>
#include <stdint.h>

// Problem constants
#define BB   4
#define NH   16
#define HD   64
#define DM   1024
#define LQ   2048
#define LK   2048
#define MTOT (BB * LQ)

// ---------------------------------------------------------------------------
// Scratch (device globals — no allocation allowed)
// ---------------------------------------------------------------------------
__device__ __half g_ahi[MTOT * DM];
__device__ __half g_alo[MTOT * DM];
__device__ __half g_whi[DM * DM];
__device__ __half g_wlo[DM * DM];
__device__ __half g_qhi[BB * NH * LQ * HD];
__device__ __half g_khi[BB * NH * LK * HD];
__device__ __half g_klo[BB * NH * LK * HD];
__device__ __half g_vh [BB * NH * LK * HD];
__device__ __half g_chi[MTOT * DM];
__device__ __half g_clo[MTOT * DM];

// ---------------------------------------------------------------------------
// Helpers
// ---------------------------------------------------------------------------
__device__ __forceinline__ unsigned pack_h2(__half a, __half b) {
    return (unsigned)__half_as_ushort(a) | ((unsigned)__half_as_ushort(b) << 16);
}

__device__ __forceinline__ void split2(float x, float y,
                                       unsigned& hi, unsigned& lo) {
    __half hx = __float2half_rn(x);
    __half hy = __float2half_rn(y);
    __half lx = __float2half_rn(x - __half2float(hx));
    __half ly = __float2half_rn(y - __half2float(hy));
    hi = pack_h2(hx, hy);
    lo = pack_h2(lx, ly);
}

__device__ __forceinline__ float ex2f(float x) {
    float y;
    asm("ex2.approx.ftz.f32 %0, %1;" : "=f"(y) : "f"(x));
    return y;
}

__device__ __forceinline__ void mma_f16(float c[4],
                                        unsigned a0, unsigned a1,
                                        unsigned a2, unsigned a3,
                                        unsigned b0, unsigned b1) {
    asm volatile(
        "mma.sync.aligned.m16n8k16.row.col.f32.f16.f16.f32 "
        "{%0,%1,%2,%3}, {%4,%5,%6,%7}, {%8,%9}, {%0,%1,%2,%3};"
        : "+f"(c[0]), "+f"(c[1]), "+f"(c[2]), "+f"(c[3])
        : "r"(a0), "r"(a1), "r"(a2), "r"(a3), "r"(b0), "r"(b1));
}

__device__ __forceinline__ uint32_t smem_u32(const void* p) {
    uint32_t a;
    asm("{ .reg .u64 t; cvta.to.shared.u64 t, %1; cvt.u32.u64 %0, t; }"
        : "=r"(a) : "l"(p));
    return a;
}

__device__ __forceinline__ void ldsm_x4(uint32_t addr, unsigned& r0,
                                        unsigned& r1, unsigned& r2,
                                        unsigned& r3) {
    asm volatile(
        "ldmatrix.sync.aligned.m8n8.x4.shared.b16 {%0,%1,%2,%3}, [%4];"
        : "=r"(r0), "=r"(r1), "=r"(r2), "=r"(r3) : "r"(addr));
}

__device__ __forceinline__ void ldsm_x4_t(uint32_t addr, unsigned& r0,
                                          unsigned& r1, unsigned& r2,
                                          unsigned& r3) {
    asm volatile(
        "ldmatrix.sync.aligned.m8n8.x4.trans.shared.b16 {%0,%1,%2,%3}, [%4];"
        : "=r"(r0), "=r"(r1), "=r"(r2), "=r"(r3) : "r"(addr));
}

__device__ __forceinline__ void cpa16(uint32_t dst, const void* src) {
    asm volatile("cp.async.cg.shared.global [%0], [%1], 16;"
                 :: "r"(dst), "l"(src) : "memory");
}
__device__ __forceinline__ void cp_commit() {
    asm volatile("cp.async.commit_group;" ::: "memory");
}
__device__ __forceinline__ void cp_waitall() {
    asm volatile("cp.async.wait_group 0;" ::: "memory");
}

#define QSCALE 0.18033688011112042f   /* 0.125 * log2(e) */

// ---------------------------------------------------------------------------
// Pre-split kernel (inputs and weights)
// ---------------------------------------------------------------------------
__global__ void split_kernel(const float4* __restrict__ src,
                             uint2* __restrict__ hi,
                             uint2* __restrict__ lo, int n4)
{
    int i = blockIdx.x * blockDim.x + threadIdx.x;
    if (i >= n4) return;
    float4 v = src[i];
    unsigned h0, l0, h1, l1;
    split2(v.x, v.y, h0, l0);
    split2(v.z, v.w, h1, l1);
    hi[i] = make_uint2(h0, h1);
    lo[i] = make_uint2(l0, l1);
}

// ---------------------------------------------------------------------------
// Split-fp16 GEMM: 128x128 tile, 256 threads / 8 warps (warp tile 32x64).
// cp.async double-buffer + ldmatrix. 16 warps/SM at 2 CTAs/SM.
// MODE 0: C fp32 [m][n] (out projection)
// MODE 2: RoPE fused + split -> (ohi, olo) head layout (K proj)
// MODE 3: plain fp16 -> ohi head layout (V proj)
// MODE 4: RoPE fused, hi only -> ohi head layout (Q proj)
// ---------------------------------------------------------------------------
#define G_STAGE 40960
#define G_AHI   0
#define G_ALO   10240
#define G_BHI   20480
#define G_BLO   30720
#define G_SMEM  (2 * G_STAGE)

template <int MODE>
__global__ void __launch_bounds__(256)
gemm_cp_kernel(const __half* __restrict__ Ahi, const __half* __restrict__ Alo,
               const __half* __restrict__ Whi, const __half* __restrict__ Wlo,
               const float* __restrict__ bias,
               const float* __restrict__ cosb, const float* __restrict__ sinb,
               float scale, float* __restrict__ outf,
               __half* __restrict__ ohi, __half* __restrict__ olo)
{
    extern __shared__ __align__(128) char smem[];
    const int tid  = threadIdx.x;
    const int warp = tid >> 5;
    const int lane = tid & 31;
    const int g = lane >> 2;
    const int t = lane & 3;
    const int wm = (warp & 3) * 32;       // 4 warps over M
    const int wn = (warp >> 2) * 64;      // 2 warps over N
    const int bm = blockIdx.y * 128;
    const int bn = blockIdx.x * 128;
    const uint32_t sb = smem_u32(smem);

    float acc[2][8][4];
#pragma unroll
    for (int i = 0; i < 2; i++)
#pragma unroll
        for (int j = 0; j < 8; j++)
#pragma unroll
            for (int c = 0; c < 4; c++) acc[i][j][c] = 0.f;

    const int lrow = tid >> 2;            // 0..63
    const int lch  = tid & 3;
#define G_ISSUE(IT)                                                          \
    do {                                                                     \
        const int kt_ = (IT) * 32;                                           \
        const uint32_t base_ = sb + ((IT) & 1) * G_STAGE;                    \
        _Pragma("unroll")                                                    \
        for (int p_ = 0; p_ < 2; p_++) {                                     \
            const int row_ = lrow + p_ * 64;                                 \
            const uint32_t d_ = row_ * 80 + lch * 16;                        \
            const size_t sa_ = (size_t)(bm + row_) * DM + kt_ + lch * 8;     \
            const size_t sb_ = (size_t)(bn + row_) * DM + kt_ + lch * 8;     \
            cpa16(base_ + G_AHI + d_, Ahi + sa_);                            \
            cpa16(base_ + G_ALO + d_, Alo + sa_);                            \
            cpa16(base_ + G_BHI + d_, Whi + sb_);                            \
            cpa16(base_ + G_BLO + d_, Wlo + sb_);                            \
        }                                                                    \
        cp_commit();                                                         \
    } while (0)

    G_ISSUE(0);
    cp_waitall();
    __syncthreads();

    for (int it = 0; it < 32; it++) {
        const uint32_t abase = sb + (it & 1) * G_STAGE;
        if (it < 31) G_ISSUE(it + 1);

#pragma unroll
        for (int kk = 0; kk < 2; kk++) {
            const uint32_t acol = kk * 32 + (lane & 16);
            const uint32_t arow = (lane & 15);
            unsigned ah[2][4], al[2][4];
#pragma unroll
            for (int i = 0; i < 2; i++) {
                const uint32_t ro = (uint32_t)(wm + 16 * i + arow) * 80 + acol;
                ldsm_x4(abase + G_AHI + ro, ah[i][0], ah[i][1], ah[i][2], ah[i][3]);
                ldsm_x4(abase + G_ALO + ro, al[i][0], al[i][1], al[i][2], al[i][3]);
            }
            const uint32_t brow = (lane & 7) + ((lane >> 4) << 3);
            const uint32_t bcol = kk * 32 + (lane & 8) * 2;
#pragma unroll
            for (int jp = 0; jp < 4; jp++) {
                const uint32_t ro = (uint32_t)(wn + 16 * jp + brow) * 80 + bcol;
                unsigned h0, h1, h2, h3, l0, l1, l2, l3;
                ldsm_x4(abase + G_BHI + ro, h0, h1, h2, h3);
                ldsm_x4(abase + G_BLO + ro, l0, l1, l2, l3);
#pragma unroll
                for (int i = 0; i < 2; i++) {
                    mma_f16(acc[i][2 * jp],     ah[i][0], ah[i][1], ah[i][2], ah[i][3], h0, h1);
                    mma_f16(acc[i][2 * jp],     ah[i][0], ah[i][1], ah[i][2], ah[i][3], l0, l1);
                    mma_f16(acc[i][2 * jp],     al[i][0], al[i][1], al[i][2], al[i][3], h0, h1);
                    mma_f16(acc[i][2 * jp + 1], ah[i][0], ah[i][1], ah[i][2], ah[i][3], h2, h3);
                    mma_f16(acc[i][2 * jp + 1], ah[i][0], ah[i][1], ah[i][2], ah[i][3], l2, l3);
                    mma_f16(acc[i][2 * jp + 1], al[i][0], al[i][1], al[i][2], al[i][3], h2, h3);
                }
            }
        }
        if (it < 31) { cp_waitall(); __syncthreads(); }
    }

    // ---- Epilogues ----
    const int h = (bn + wn) >> 6;   // head for this warp's N-tile (N=64 = 1 head)

    if (MODE == 0) {
#pragma unroll
        for (int i = 0; i < 2; i++) {
#pragma unroll
            for (int j = 0; j < 8; j++) {
                const int n = bn + wn + 8 * j + 2 * t;
                const float b0 = bias[n];
                const float b1 = bias[n + 1];
#pragma unroll
                for (int half = 0; half < 2; half++) {
                    const int m = bm + wm + 16 * i + g + half * 8;
                    float2 val;
                    val.x = acc[i][j][half * 2 + 0] + b0;
                    val.y = acc[i][j][half * 2 + 1] + b1;
                    *reinterpret_cast<float2*>(outf + (size_t)m * DM + n) = val;
                }
            }
        }
    } else if (MODE == 2 || MODE == 4) {
        // RoPE (+ optional split). Pair: col dd (j<4) with col dd+32 (j+4).
#pragma unroll
        for (int i = 0; i < 2; i++) {
#pragma unroll
            for (int half = 0; half < 2; half++) {
                const int m = bm + wm + 16 * i + g + half * 8;
                const int b = m >> 11;
                const int l = m & (LQ - 1);
                const size_t rowoff = (((size_t)(b * NH + h)) * LQ + l) * HD;
                const float* cr = cosb + ((size_t)b * LQ + l) * HD;
                const float* sr = sinb + ((size_t)b * LQ + l) * HD;
#pragma unroll
                for (int j = 0; j < 4; j++) {
                    const int dd = 8 * j + 2 * t;
                    const int n1 = bn + wn + dd;
                    float x1a = acc[i][j][half * 2 + 0] + bias[n1];
                    float x1b = acc[i][j][half * 2 + 1] + bias[n1 + 1];
                    float x2a = acc[i][j + 4][half * 2 + 0] + bias[n1 + 32];
                    float x2b = acc[i][j + 4][half * 2 + 1] + bias[n1 + 33];
                    float y1a = (x1a * cr[dd]      - x2a * sr[dd])      * scale;
                    float y1b = (x1b * cr[dd + 1]  - x2b * sr[dd + 1])  * scale;
                    float y2a = (x2a * cr[dd + 32] + x1a * sr[dd + 32]) * scale;
                    float y2b = (x2b * cr[dd + 33] + x1b * sr[dd + 33]) * scale;
                    if (MODE == 2) {
                        unsigned h1, l1, h2, l2;
                        split2(y1a, y1b, h1, l1);
                        split2(y2a, y2b, h2, l2);
                        *reinterpret_cast<unsigned*>(ohi + rowoff + dd)      = h1;
                        *reinterpret_cast<unsigned*>(olo + rowoff + dd)      = l1;
                        *reinterpret_cast<unsigned*>(ohi + rowoff + dd + 32) = h2;
                        *reinterpret_cast<unsigned*>(olo + rowoff + dd + 32) = l2;
                    } else {
                        *reinterpret_cast<unsigned*>(ohi + rowoff + dd) =
                            pack_h2(__float2half_rn(y1a), __float2half_rn(y1b));
                        *reinterpret_cast<unsigned*>(ohi + rowoff + dd + 32) =
                            pack_h2(__float2half_rn(y2a), __float2half_rn(y2b));
                    }
                }
            }
        }
    } else {  // MODE 3: plain fp16 head layout (V)
#pragma unroll
        for (int i = 0; i < 2; i++) {
#pragma unroll
            for (int half = 0; half < 2; half++) {
                const int m = bm + wm + 16 * i + g + half * 8;
                const int b = m >> 11;
                const int l = m & (LQ - 1);
                const size_t rowoff = (((size_t)(b * NH + h)) * LQ + l) * HD;
#pragma unroll
                for (int j = 0; j < 8; j++) {
                    const int dd = 8 * j + 2 * t;
                    const int n = bn + wn + dd;
                    float vx = acc[i][j][half * 2 + 0] + bias[n];
                    float vy = acc[i][j][half * 2 + 1] + bias[n + 1];
                    *reinterpret_cast<unsigned*>(ohi + rowoff + dd) =
                        pack_h2(__float2half_rn(vx), __float2half_rn(vy));
                }
            }
        }
    }
#undef G_ISSUE
}

// ---------------------------------------------------------------------------
// Flash attention, BK=64, 2-MMA QK^T (q_hi*k_hi + q_hi*k_lo; q_lo dropped).
// Q plain fp16 (scale*log2e folded). cp.async double-buffer, ldmatrix,
// Q hoisted, P register-direct, ex2 softmax. Writes split ctx.
// One block = (b,h) x 64 Q rows; 4 warps x 16 rows; 32 iters of 64 keys.
// ---------------------------------------------------------------------------
#define F_STG   27776
#define F_QHI   0
#define F_KHI(s) (9216 + (s) * F_STG)
#define F_KLO(s) (F_KHI(s) + 9216)
#define F_VH(s)  (F_KHI(s) + 18432)
#define F_MSK(s) (F_KHI(s) + 27648)
#define F_SMEM  (9216 + 2 * F_STG)

__global__ void __launch_bounds__(128)
flash_bk64_kernel(const __half* __restrict__ qhi,
                  const __half* __restrict__ khi, const __half* __restrict__ klo,
                  const __half* __restrict__ vh,
                  const unsigned char* __restrict__ mask,
                  __half* __restrict__ chi, __half* __restrict__ clo)
{
    extern __shared__ __align__(128) char smem[];
    const int tid  = threadIdx.x;
    const int warp = tid >> 5;
    const int lane = tid & 31;
    const int g = lane >> 2;
    const int t = lane & 3;
    const int m0 = warp * 16;

    const int bh = blockIdx.y;
    const int b  = bh >> 4;
    const int h  = bh & 15;
    const int q0 = blockIdx.x * 64;
    const uint32_t sb = smem_u32(smem);

    const __half* qh_g = qhi + (((size_t)bh) * LQ + q0) * HD;
    const size_t kvbase = ((size_t)bh) * LK * HD;

    const int lrow = tid >> 3;   // 0..15
    const int lch  = tid & 7;

#define F_ISSUE(IT)                                                          \
    do {                                                                     \
        const int kt_ = (IT) * 64;                                           \
        const int st_ = (IT) & 1;                                            \
        _Pragma("unroll")                                                    \
        for (int p_ = 0; p_ < 4; p_++) {                                     \
            const int row_ = lrow + p_ * 16;                                 \
            const uint32_t d_ = row_ * 144 + lch * 16;                       \
            const size_t s_ = kvbase + (size_t)(kt_ + row_) * HD + lch * 8;  \
            cpa16(sb + F_KHI(st_) + d_, khi + s_);                           \
            cpa16(sb + F_KLO(st_) + d_, klo + s_);                           \
            cpa16(sb + F_VH(st_)  + d_, vh  + s_);                           \
        }                                                                    \
        if (tid < 4)                                                         \
            cpa16(sb + F_MSK(st_) + tid * 16,                                \
                  mask + (size_t)b * LK + kt_ + tid * 16);                   \
        cp_commit();                                                         \
    } while (0)

    // Prologue: Q tile + stage 0
#pragma unroll
    for (int p = 0; p < 4; p++) {
        const int row = lrow + p * 16;
        const uint32_t d = row * 144 + lch * 16;
        cpa16(sb + F_QHI + d, qh_g + (size_t)row * HD + lch * 8);
    }
    F_ISSUE(0);
    cp_waitall();
    __syncthreads();

    unsigned qh[4][4];
    {
        const uint32_t qoff = (uint32_t)(m0 + (lane & 15)) * 144 + (lane & 16);
#pragma unroll
        for (int kk = 0; kk < 4; kk++)
            ldsm_x4(sb + F_QHI + qoff + kk * 32,
                    qh[kk][0], qh[kk][1], qh[kk][2], qh[kk][3]);
    }

    float m_[2] = { -1e30f, -1e30f };
    float l_[2] = { 0.f, 0.f };
    float o[8][4];
#pragma unroll
    for (int n = 0; n < 8; n++)
#pragma unroll
        for (int c = 0; c < 4; c++) o[n][c] = 0.f;

    for (int it = 0; it < LK / 64; it++) {
        const int st = it & 1;
        if (it < LK / 64 - 1) F_ISSUE(it + 1);

        // S = Q*K^T : 2 MMAs per fragment pair
        float s[8][4];
#pragma unroll
        for (int j = 0; j < 8; j++)
#pragma unroll
            for (int c = 0; c < 4; c++) s[j][c] = 0.f;

        const uint32_t krow = (lane & 7) + ((lane >> 4) << 3);
#pragma unroll
        for (int kk = 0; kk < 4; kk++) {
            const uint32_t kcol = kk * 32 + (lane & 8) * 2;
#pragma unroll
            for (int jp = 0; jp < 4; jp++) {
                const uint32_t ro = (uint32_t)(jp * 16 + krow) * 144 + kcol;
                unsigned h0, h1, h2, h3, l0, l1, l2, l3;
                ldsm_x4(sb + F_KHI(st) + ro, h0, h1, h2, h3);
                ldsm_x4(sb + F_KLO(st) + ro, l0, l1, l2, l3);
                mma_f16(s[2 * jp],     qh[kk][0], qh[kk][1], qh[kk][2], qh[kk][3], h0, h1);
                mma_f16(s[2 * jp],     qh[kk][0], qh[kk][1], qh[kk][2], qh[kk][3], l0, l1);
                mma_f16(s[2 * jp + 1], qh[kk][0], qh[kk][1], qh[kk][2], qh[kk][3], h2, h3);
                mma_f16(s[2 * jp + 1], qh[kk][0], qh[kk][1], qh[kk][2], qh[kk][3], l2, l3);
            }
        }

        // Mask
        const unsigned char* msk =
            reinterpret_cast<const unsigned char*>(smem) + F_MSK(st);
#pragma unroll
        for (int j = 0; j < 8; j++) {
            const int col = j * 8 + 2 * t;
            if (msk[col])     { s[j][0] = -1e30f; s[j][2] = -1e30f; }
            if (msk[col + 1]) { s[j][1] = -1e30f; s[j][3] = -1e30f; }
        }

        // Online softmax (base-2 domain)
        float r0 = -1e30f, r1 = -1e30f;
#pragma unroll
        for (int j = 0; j < 8; j++) {
            r0 = fmaxf(r0, fmaxf(s[j][0], s[j][1]));
            r1 = fmaxf(r1, fmaxf(s[j][2], s[j][3]));
        }
        r0 = fmaxf(r0, __shfl_xor_sync(0xffffffffu, r0, 1));
        r0 = fmaxf(r0, __shfl_xor_sync(0xffffffffu, r0, 2));
        r1 = fmaxf(r1, __shfl_xor_sync(0xffffffffu, r1, 1));
        r1 = fmaxf(r1, __shfl_xor_sync(0xffffffffu, r1, 2));

        const float mn0 = fmaxf(m_[0], r0);
        const float mn1 = fmaxf(m_[1], r1);
        const float alpha0 = ex2f(m_[0] - mn0);
        const float alpha1 = ex2f(m_[1] - mn1);
        m_[0] = mn0; m_[1] = mn1;

        float sum0 = 0.f, sum1 = 0.f;
#pragma unroll
        for (int j = 0; j < 8; j++) {
            s[j][0] = ex2f(s[j][0] - mn0);
            s[j][1] = ex2f(s[j][1] - mn0);
            s[j][2] = ex2f(s[j][2] - mn1);
            s[j][3] = ex2f(s[j][3] - mn1);
            sum0 += s[j][0] + s[j][1];
            sum1 += s[j][2] + s[j][3];
        }
        sum0 += __shfl_xor_sync(0xffffffffu, sum0, 1);
        sum0 += __shfl_xor_sync(0xffffffffu, sum0, 2);
        sum1 += __shfl_xor_sync(0xffffffffu, sum1, 1);
        sum1 += __shfl_xor_sync(0xffffffffu, sum1, 2);
        l_[0] = l_[0] * alpha0 + sum0;
        l_[1] = l_[1] * alpha1 + sum1;

#pragma unroll
        for (int n = 0; n < 8; n++) {
            o[n][0] *= alpha0; o[n][1] *= alpha0;
            o[n][2] *= alpha1; o[n][3] *= alpha1;
        }

        // O += P*V ; P register-direct
        const uint32_t vrow = (lane & 15);
        const uint32_t vcolb = (lane & 16);
#pragma unroll
        for (int kk = 0; kk < 4; kk++) {
            const unsigned a0 = pack_h2(__float2half_rn(s[2 * kk][0]),
                                        __float2half_rn(s[2 * kk][1]));
            const unsigned a1 = pack_h2(__float2half_rn(s[2 * kk][2]),
                                        __float2half_rn(s[2 * kk][3]));
            const unsigned a2 = pack_h2(__float2half_rn(s[2 * kk + 1][0]),
                                        __float2half_rn(s[2 * kk + 1][1]));
            const unsigned a3 = pack_h2(__float2half_rn(s[2 * kk + 1][2]),
                                        __float2half_rn(s[2 * kk + 1][3]));
            const uint32_t rbase = (uint32_t)(kk * 16 + vrow) * 144 + vcolb;
#pragma unroll
            for (int np = 0; np < 4; np++) {
                unsigned r0v, r1v, r2v, r3v;
                ldsm_x4_t(sb + F_VH(st) + rbase + np * 32, r0v, r1v, r2v, r3v);
                mma_f16(o[2 * np],     a0, a1, a2, a3, r0v, r1v);
                mma_f16(o[2 * np + 1], a0, a1, a2, a3, r2v, r3v);
            }
        }

        if (it < LK / 64 - 1) { cp_waitall(); __syncthreads(); }
    }

    // Epilogue: normalize, split, write ctx hi/lo
    const float inv0 = 1.f / l_[0];
    const float inv1 = 1.f / l_[1];
#pragma unroll
    for (int n = 0; n < 8; n++) {
        const int col = h * HD + n * 8 + 2 * t;
        const int row0 = q0 + m0 + g;
        const size_t off0 = ((size_t)b * LQ + row0) * DM + col;
        const size_t off1 = ((size_t)b * LQ + row0 + 8) * DM + col;
        unsigned hi0, lo0, hi1, lo1;
        split2(o[n][0] * inv0, o[n][1] * inv0, hi0, lo0);
        split2(o[n][2] * inv1, o[n][3] * inv1, hi1, lo1);
        *reinterpret_cast<unsigned*>(chi + off0) = hi0;
        *reinterpret_cast<unsigned*>(clo + off0) = lo0;
        *reinterpret_cast<unsigned*>(chi + off1) = hi1;
        *reinterpret_cast<unsigned*>(clo + off1) = lo1;
    }
#undef F_ISSUE
}

// ---------------------------------------------------------------------------
// Launch
// ---------------------------------------------------------------------------
extern "C" void kernel_launch(void* const* d_in, const int* in_sizes, int n_in,
                              void* d_out, int out_size)
{
    const float* query = (const float*)d_in[0];
    const float* key   = (const float*)d_in[1];
    const float* value = (const float*)d_in[2];
    const float* cos_q = (const float*)d_in[3];
    const float* sin_q = (const float*)d_in[4];
    const float* cos_k = (const float*)d_in[5];
    const float* sin_k = (const float*)d_in[6];
    const unsigned char* mask = (const unsigned char*)d_in[7];
    const float* Wq = (const float*)d_in[8];
    const float* bq = (const float*)d_in[9];
    const float* Wk = (const float*)d_in[10];
    const float* bk = (const float*)d_in[11];
    const float* Wv = (const float*)d_in[12];
    const float* bv = (const float*)d_in[13];
    const float* Wo = (const float*)d_in[14];
    const float* bo = (const float*)d_in[15];
    float* out = (float*)d_out;

    __half *pahi, *palo, *pwhi, *pwlo;
    __half *pqhi, *pkhi, *pklo, *pvh, *pchi, *pclo;
    cudaGetSymbolAddress((void**)&pahi, g_ahi);
    cudaGetSymbolAddress((void**)&palo, g_alo);
    cudaGetSymbolAddress((void**)&pwhi, g_whi);
    cudaGetSymbolAddress((void**)&pwlo, g_wlo);
    cudaGetSymbolAddress((void**)&pqhi, g_qhi);
    cudaGetSymbolAddress((void**)&pkhi, g_khi);
    cudaGetSymbolAddress((void**)&pklo, g_klo);
    cudaGetSymbolAddress((void**)&pvh,  g_vh);
    cudaGetSymbolAddress((void**)&pchi, g_chi);
    cudaGetSymbolAddress((void**)&pclo, g_clo);

    cudaFuncSetAttribute(gemm_cp_kernel<0>,
                         cudaFuncAttributeMaxDynamicSharedMemorySize, G_SMEM);
    cudaFuncSetAttribute(gemm_cp_kernel<2>,
                         cudaFuncAttributeMaxDynamicSharedMemorySize, G_SMEM);
    cudaFuncSetAttribute(gemm_cp_kernel<3>,
                         cudaFuncAttributeMaxDynamicSharedMemorySize, G_SMEM);
    cudaFuncSetAttribute(gemm_cp_kernel<4>,
                         cudaFuncAttributeMaxDynamicSharedMemorySize, G_SMEM);
    cudaFuncSetAttribute(flash_bk64_kernel,
                         cudaFuncAttributeMaxDynamicSharedMemorySize, F_SMEM);

    const int nA4 = MTOT * DM / 4;
    const int nW4 = DM * DM / 4;
    dim3 gg(DM / 128, MTOT / 128);   // (8, 64)

    // Q projection (+RoPE, hi only, scale = 0.125*log2e folded)
    split_kernel<<<(nA4 + 255) / 256, 256>>>((const float4*)query,
                                             (uint2*)pahi, (uint2*)palo, nA4);
    split_kernel<<<(nW4 + 255) / 256, 256>>>((const float4*)Wq,
                                             (uint2*)pwhi, (uint2*)pwlo, nW4);
    gemm_cp_kernel<4><<<gg, 256, G_SMEM>>>(pahi, palo, pwhi, pwlo, bq,
                                           cos_q, sin_q, QSCALE,
                                           nullptr, pqhi, nullptr);

    // K projection (+RoPE, split hi/lo)
    split_kernel<<<(nA4 + 255) / 256, 256>>>((const float4*)key,
                                             (uint2*)pahi, (uint2*)palo, nA4);
    split_kernel<<<(nW4 + 255) / 256, 256>>>((const float4*)Wk,
                                             (uint2*)pwhi, (uint2*)pwlo, nW4);
    gemm_cp_kernel<2><<<gg, 256, G_SMEM>>>(pahi, palo, pwhi, pwlo, bk,
                                           cos_k, sin_k, 1.0f,
                                           nullptr, pkhi, pklo);

    // V projection (fp16 direct)
    split_kernel<<<(nA4 + 255) / 256, 256>>>((const float4*)value,
                                             (uint2*)pahi, (uint2*)palo, nA4);
    split_kernel<<<(nW4 + 255) / 256, 256>>>((const float4*)Wv,
                                             (uint2*)pwhi, (uint2*)pwlo, nW4);
    gemm_cp_kernel<3><<<gg, 256, G_SMEM>>>(pahi, palo, pwhi, pwlo, bv,
                                           nullptr, nullptr, 1.0f,
                                           nullptr, pvh, nullptr);

    // Attention (2-MMA QK, writes split ctx)
    flash_bk64_kernel<<<dim3(LQ / 64, BB * NH), 128, F_SMEM>>>(
        pqhi, pkhi, pklo, pvh, mask, pchi, pclo);

    // Output projection (A = split ctx)
    split_kernel<<<(nW4 + 255) / 256, 256>>>((const float4*)Wo,
                                             (uint2*)pwhi, (uint2*)pwlo, nW4);
    gemm_cp_kernel<0><<<gg, 256, G_SMEM>>>(pchi, pclo, pwhi, pwlo, bo,
                                           nullptr, nullptr, 1.0f,
                                           out, nullptr, nullptr);
}

// round 10
// speedup vs baseline: 3.9319x; 1.0115x over previous
#include <cuda_runtime.h>
#include <cuda_fp16.h>
#include <math.h>
#include <stdint.h>

// Problem constants
#define BB   4
#define NH   16
#define HD   64
#define DM   1024
#define LQ   2048
#define LK   2048
#define MTOT (BB * LQ)

// ---------------------------------------------------------------------------
// Scratch (device globals — no allocation allowed)
// ---------------------------------------------------------------------------
__device__ __half g_ahi[MTOT * DM];
__device__ __half g_alo[MTOT * DM];
__device__ __half g_whi[DM * DM];
__device__ __half g_wlo[DM * DM];
__device__ __half g_qhi[BB * NH * LQ * HD];
__device__ __half g_khi[BB * NH * LK * HD];
__device__ __half g_klo[BB * NH * LK * HD];
__device__ __half g_vh [BB * NH * LK * HD];
__device__ __half g_chi[MTOT * DM];
__device__ __half g_clo[MTOT * DM];

// ---------------------------------------------------------------------------
// Helpers
// ---------------------------------------------------------------------------
__device__ __forceinline__ unsigned pack_h2(__half a, __half b) {
    return (unsigned)__half_as_ushort(a) | ((unsigned)__half_as_ushort(b) << 16);
}

__device__ __forceinline__ void split2(float x, float y,
                                       unsigned& hi, unsigned& lo) {
    __half hx = __float2half_rn(x);
    __half hy = __float2half_rn(y);
    __half lx = __float2half_rn(x - __half2float(hx));
    __half ly = __float2half_rn(y - __half2float(hy));
    hi = pack_h2(hx, hy);
    lo = pack_h2(lx, ly);
}

__device__ __forceinline__ float ex2f(float x) {
    float y;
    asm("ex2.approx.ftz.f32 %0, %1;" : "=f"(y) : "f"(x));
    return y;
}

// pack two floats into f16x2 (lo -> low half), then 2^x elementwise in fp16
__device__ __forceinline__ unsigned f22h2(float lo, float hi) {
    unsigned r;
    asm("cvt.rn.f16x2.f32 %0, %1, %2;" : "=r"(r) : "f"(hi), "f"(lo));
    return r;
}
__device__ __forceinline__ unsigned h2ex2(unsigned x) {
    unsigned y;
    asm("ex2.approx.f16x2 %0, %1;" : "=r"(y) : "r"(x));
    return y;
}

__device__ __forceinline__ void mma_f16(float c[4],
                                        unsigned a0, unsigned a1,
                                        unsigned a2, unsigned a3,
                                        unsigned b0, unsigned b1) {
    asm volatile(
        "mma.sync.aligned.m16n8k16.row.col.f32.f16.f16.f32 "
        "{%0,%1,%2,%3}, {%4,%5,%6,%7}, {%8,%9}, {%0,%1,%2,%3};"
        : "+f"(c[0]), "+f"(c[1]), "+f"(c[2]), "+f"(c[3])
        : "r"(a0), "r"(a1), "r"(a2), "r"(a3), "r"(b0), "r"(b1));
}

__device__ __forceinline__ uint32_t smem_u32(const void* p) {
    uint32_t a;
    asm("{ .reg .u64 t; cvta.to.shared.u64 t, %1; cvt.u32.u64 %0, t; }"
        : "=r"(a) : "l"(p));
    return a;
}

__device__ __forceinline__ void ldsm_x4(uint32_t addr, unsigned& r0,
                                        unsigned& r1, unsigned& r2,
                                        unsigned& r3) {
    asm volatile(
        "ldmatrix.sync.aligned.m8n8.x4.shared.b16 {%0,%1,%2,%3}, [%4];"
        : "=r"(r0), "=r"(r1), "=r"(r2), "=r"(r3) : "r"(addr));
}

__device__ __forceinline__ void ldsm_x4_t(uint32_t addr, unsigned& r0,
                                          unsigned& r1, unsigned& r2,
                                          unsigned& r3) {
    asm volatile(
        "ldmatrix.sync.aligned.m8n8.x4.trans.shared.b16 {%0,%1,%2,%3}, [%4];"
        : "=r"(r0), "=r"(r1), "=r"(r2), "=r"(r3) : "r"(addr));
}

__device__ __forceinline__ void cpa16(uint32_t dst, const void* src) {
    asm volatile("cp.async.cg.shared.global [%0], [%1], 16;"
                 :: "r"(dst), "l"(src) : "memory");
}
__device__ __forceinline__ void cp_commit() {
    asm volatile("cp.async.commit_group;" ::: "memory");
}
__device__ __forceinline__ void cp_waitall() {
    asm volatile("cp.async.wait_group 0;" ::: "memory");
}

#define QSCALE 0.18033688011112042f   /* 0.125 * log2(e) */
#define ONESH2 0x3C003C00u            /* half2(1.0, 1.0) */

// ---------------------------------------------------------------------------
// Pre-split kernel (inputs and weights)
// ---------------------------------------------------------------------------
__global__ void split_kernel(const float4* __restrict__ src,
                             uint2* __restrict__ hi,
                             uint2* __restrict__ lo, int n4)
{
    int i = blockIdx.x * blockDim.x + threadIdx.x;
    if (i >= n4) return;
    float4 v = src[i];
    unsigned h0, l0, h1, l1;
    split2(v.x, v.y, h0, l0);
    split2(v.z, v.w, h1, l1);
    hi[i] = make_uint2(h0, h1);
    lo[i] = make_uint2(l0, l1);
}

// ---------------------------------------------------------------------------
// Split-fp16 GEMM: 256x128 tile, 256 threads / 8 warps, warp tile 64x64.
// cp.async double-buffer + ldmatrix. L2 traffic: A re-read 8x, B 32x.
// MODE 0: C fp32 [m][n] (out projection)
// MODE 2: RoPE fused + split -> (ohi, olo) head layout (K proj)
// MODE 3: plain fp16 -> ohi head layout (V proj)
// MODE 4: RoPE fused, hi only -> ohi head layout (Q proj)
// ---------------------------------------------------------------------------
#define G_STAGE 61440
#define G_AHI   0            /* 256 rows x 80B = 20480 */
#define G_ALO   20480
#define G_BHI   40960        /* 128 rows x 80B = 10240 */
#define G_BLO   51200
#define G_SMEM  (2 * G_STAGE)   /* 122880 */

template <int MODE>
__global__ void __launch_bounds__(256)
gemm_cp_kernel(const __half* __restrict__ Ahi, const __half* __restrict__ Alo,
               const __half* __restrict__ Whi, const __half* __restrict__ Wlo,
               const float* __restrict__ bias,
               const float* __restrict__ cosb, const float* __restrict__ sinb,
               float scale, float* __restrict__ outf,
               __half* __restrict__ ohi, __half* __restrict__ olo)
{
    extern __shared__ __align__(128) char smem[];
    const int tid  = threadIdx.x;
    const int warp = tid >> 5;
    const int lane = tid & 31;
    const int g = lane >> 2;
    const int t = lane & 3;
    const int wm = (warp & 3) * 64;       // 4 warps over M (256)
    const int wn = (warp >> 2) * 64;      // 2 warps over N (128)
    const int bm = blockIdx.y * 256;
    const int bn = blockIdx.x * 128;
    const uint32_t sb = smem_u32(smem);

    float acc[4][8][4];
#pragma unroll
    for (int i = 0; i < 4; i++)
#pragma unroll
        for (int j = 0; j < 8; j++)
#pragma unroll
            for (int c = 0; c < 4; c++) acc[i][j][c] = 0.f;

    const int lrow = tid >> 2;            // 0..63
    const int lch  = tid & 3;
#define G_ISSUE(IT)                                                          \
    do {                                                                     \
        const int kt_ = (IT) * 32;                                           \
        const uint32_t base_ = sb + ((IT) & 1) * G_STAGE;                    \
        _Pragma("unroll")                                                    \
        for (int p_ = 0; p_ < 4; p_++) {                                     \
            const int row_ = lrow + p_ * 64;                                 \
            const uint32_t d_ = row_ * 80 + lch * 16;                        \
            const size_t sa_ = (size_t)(bm + row_) * DM + kt_ + lch * 8;     \
            cpa16(base_ + G_AHI + d_, Ahi + sa_);                            \
            cpa16(base_ + G_ALO + d_, Alo + sa_);                            \
        }                                                                    \
        _Pragma("unroll")                                                    \
        for (int p_ = 0; p_ < 2; p_++) {                                     \
            const int row_ = lrow + p_ * 64;                                 \
            const uint32_t d_ = row_ * 80 + lch * 16;                        \
            const size_t sb_ = (size_t)(bn + row_) * DM + kt_ + lch * 8;     \
            cpa16(base_ + G_BHI + d_, Whi + sb_);                            \
            cpa16(base_ + G_BLO + d_, Wlo + sb_);                            \
        }                                                                    \
        cp_commit();                                                         \
    } while (0)

    G_ISSUE(0);
    cp_waitall();
    __syncthreads();

    for (int it = 0; it < 32; it++) {
        const uint32_t abase = sb + (it & 1) * G_STAGE;
        if (it < 31) G_ISSUE(it + 1);

#pragma unroll
        for (int kk = 0; kk < 2; kk++) {
            const uint32_t acol = kk * 32 + (lane & 16);
            const uint32_t arow = (lane & 15);
            unsigned ah[4][4], al[4][4];
#pragma unroll
            for (int i = 0; i < 4; i++) {
                const uint32_t ro = (uint32_t)(wm + 16 * i + arow) * 80 + acol;
                ldsm_x4(abase + G_AHI + ro, ah[i][0], ah[i][1], ah[i][2], ah[i][3]);
                ldsm_x4(abase + G_ALO + ro, al[i][0], al[i][1], al[i][2], al[i][3]);
            }
            const uint32_t brow = (lane & 7) + ((lane >> 4) << 3);
            const uint32_t bcol = kk * 32 + (lane & 8) * 2;
#pragma unroll
            for (int jp = 0; jp < 4; jp++) {
                const uint32_t ro = (uint32_t)(wn + 16 * jp + brow) * 80 + bcol;
                unsigned h0, h1, h2, h3, l0, l1, l2, l3;
                ldsm_x4(abase + G_BHI + ro, h0, h1, h2, h3);
                ldsm_x4(abase + G_BLO + ro, l0, l1, l2, l3);
#pragma unroll
                for (int i = 0; i < 4; i++) {
                    mma_f16(acc[i][2 * jp],     ah[i][0], ah[i][1], ah[i][2], ah[i][3], h0, h1);
                    mma_f16(acc[i][2 * jp],     ah[i][0], ah[i][1], ah[i][2], ah[i][3], l0, l1);
                    mma_f16(acc[i][2 * jp],     al[i][0], al[i][1], al[i][2], al[i][3], h0, h1);
                    mma_f16(acc[i][2 * jp + 1], ah[i][0], ah[i][1], ah[i][2], ah[i][3], h2, h3);
                    mma_f16(acc[i][2 * jp + 1], ah[i][0], ah[i][1], ah[i][2], ah[i][3], l2, l3);
                    mma_f16(acc[i][2 * jp + 1], al[i][0], al[i][1], al[i][2], al[i][3], h2, h3);
                }
            }
        }
        if (it < 31) { cp_waitall(); __syncthreads(); }
    }

    // ---- Epilogues ----
    const int h = (bn + wn) >> 6;   // head for this warp's N-tile (N=64 = 1 head)

    if (MODE == 0) {
#pragma unroll
        for (int i = 0; i < 4; i++) {
#pragma unroll
            for (int j = 0; j < 8; j++) {
                const int n = bn + wn + 8 * j + 2 * t;
                const float b0 = bias[n];
                const float b1 = bias[n + 1];
#pragma unroll
                for (int half = 0; half < 2; half++) {
                    const int m = bm + wm + 16 * i + g + half * 8;
                    float2 val;
                    val.x = acc[i][j][half * 2 + 0] + b0;
                    val.y = acc[i][j][half * 2 + 1] + b1;
                    *reinterpret_cast<float2*>(outf + (size_t)m * DM + n) = val;
                }
            }
        }
    } else if (MODE == 2 || MODE == 4) {
        // RoPE (+ optional split). Pair: col dd (j<4) with col dd+32 (j+4).
#pragma unroll
        for (int i = 0; i < 4; i++) {
#pragma unroll
            for (int half = 0; half < 2; half++) {
                const int m = bm + wm + 16 * i + g + half * 8;
                const int b = m >> 11;
                const int l = m & (LQ - 1);
                const size_t rowoff = (((size_t)(b * NH + h)) * LQ + l) * HD;
                const float* cr = cosb + ((size_t)b * LQ + l) * HD;
                const float* sr = sinb + ((size_t)b * LQ + l) * HD;
#pragma unroll
                for (int j = 0; j < 4; j++) {
                    const int dd = 8 * j + 2 * t;
                    const int n1 = bn + wn + dd;
                    float x1a = acc[i][j][half * 2 + 0] + bias[n1];
                    float x1b = acc[i][j][half * 2 + 1] + bias[n1 + 1];
                    float x2a = acc[i][j + 4][half * 2 + 0] + bias[n1 + 32];
                    float x2b = acc[i][j + 4][half * 2 + 1] + bias[n1 + 33];
                    float y1a = (x1a * cr[dd]      - x2a * sr[dd])      * scale;
                    float y1b = (x1b * cr[dd + 1]  - x2b * sr[dd + 1])  * scale;
                    float y2a = (x2a * cr[dd + 32] + x1a * sr[dd + 32]) * scale;
                    float y2b = (x2b * cr[dd + 33] + x1b * sr[dd + 33]) * scale;
                    if (MODE == 2) {
                        unsigned h1, l1, h2, l2;
                        split2(y1a, y1b, h1, l1);
                        split2(y2a, y2b, h2, l2);
                        *reinterpret_cast<unsigned*>(ohi + rowoff + dd)      = h1;
                        *reinterpret_cast<unsigned*>(olo + rowoff + dd)      = l1;
                        *reinterpret_cast<unsigned*>(ohi + rowoff + dd + 32) = h2;
                        *reinterpret_cast<unsigned*>(olo + rowoff + dd + 32) = l2;
                    } else {
                        *reinterpret_cast<unsigned*>(ohi + rowoff + dd) =
                            pack_h2(__float2half_rn(y1a), __float2half_rn(y1b));
                        *reinterpret_cast<unsigned*>(ohi + rowoff + dd + 32) =
                            pack_h2(__float2half_rn(y2a), __float2half_rn(y2b));
                    }
                }
            }
        }
    } else {  // MODE 3: plain fp16 head layout (V)
#pragma unroll
        for (int i = 0; i < 4; i++) {
#pragma unroll
            for (int half = 0; half < 2; half++) {
                const int m = bm + wm + 16 * i + g + half * 8;
                const int b = m >> 11;
                const int l = m & (LQ - 1);
                const size_t rowoff = (((size_t)(b * NH + h)) * LQ + l) * HD;
#pragma unroll
                for (int j = 0; j < 8; j++) {
                    const int dd = 8 * j + 2 * t;
                    const int n = bn + wn + dd;
                    float vx = acc[i][j][half * 2 + 0] + bias[n];
                    float vy = acc[i][j][half * 2 + 1] + bias[n + 1];
                    *reinterpret_cast<unsigned*>(ohi + rowoff + dd) =
                        pack_h2(__float2half_rn(vx), __float2half_rn(vy));
                }
            }
        }
    }
#undef G_ISSUE
}

// ---------------------------------------------------------------------------
// Flash attention, BK=64, 2-MMA QK^T. fp16x2 ex2 softmax; row sums via
// ones-column MMA (consistent fp16 P for numerator and denominator).
// One block = (b,h) x 64 Q rows; 4 warps x 16 rows; 32 iters of 64 keys.
// ---------------------------------------------------------------------------
#define F_STG   27776
#define F_QHI   0
#define F_KHI(s) (9216 + (s) * F_STG)
#define F_KLO(s) (F_KHI(s) + 9216)
#define F_VH(s)  (F_KHI(s) + 18432)
#define F_MSK(s) (F_KHI(s) + 27648)
#define F_SMEM  (9216 + 2 * F_STG)

__global__ void __launch_bounds__(128)
flash_bk64_kernel(const __half* __restrict__ qhi,
                  const __half* __restrict__ khi, const __half* __restrict__ klo,
                  const __half* __restrict__ vh,
                  const unsigned char* __restrict__ mask,
                  __half* __restrict__ chi, __half* __restrict__ clo)
{
    extern __shared__ __align__(128) char smem[];
    const int tid  = threadIdx.x;
    const int warp = tid >> 5;
    const int lane = tid & 31;
    const int g = lane >> 2;
    const int t = lane & 3;
    const int m0 = warp * 16;

    const int bh = blockIdx.y;
    const int b  = bh >> 4;
    const int h  = bh & 15;
    const int q0 = blockIdx.x * 64;
    const uint32_t sb = smem_u32(smem);

    const __half* qh_g = qhi + (((size_t)bh) * LQ + q0) * HD;
    const size_t kvbase = ((size_t)bh) * LK * HD;

    const int lrow = tid >> 3;   // 0..15
    const int lch  = tid & 7;

#define F_ISSUE(IT)                                                          \
    do {                                                                     \
        const int kt_ = (IT) * 64;                                           \
        const int st_ = (IT) & 1;                                            \
        _Pragma("unroll")                                                    \
        for (int p_ = 0; p_ < 4; p_++) {                                     \
            const int row_ = lrow + p_ * 16;                                 \
            const uint32_t d_ = row_ * 144 + lch * 16;                       \
            const size_t s_ = kvbase + (size_t)(kt_ + row_) * HD + lch * 8;  \
            cpa16(sb + F_KHI(st_) + d_, khi + s_);                           \
            cpa16(sb + F_KLO(st_) + d_, klo + s_);                           \
            cpa16(sb + F_VH(st_)  + d_, vh  + s_);                           \
        }                                                                    \
        if (tid < 4)                                                         \
            cpa16(sb + F_MSK(st_) + tid * 16,                                \
                  mask + (size_t)b * LK + kt_ + tid * 16);                   \
        cp_commit();                                                         \
    } while (0)

    // Prologue: Q tile + stage 0
#pragma unroll
    for (int p = 0; p < 4; p++) {
        const int row = lrow + p * 16;
        const uint32_t d = row * 144 + lch * 16;
        cpa16(sb + F_QHI + d, qh_g + (size_t)row * HD + lch * 8);
    }
    F_ISSUE(0);
    cp_waitall();
    __syncthreads();

    unsigned qh[4][4];
    {
        const uint32_t qoff = (uint32_t)(m0 + (lane & 15)) * 144 + (lane & 16);
#pragma unroll
        for (int kk = 0; kk < 4; kk++)
            ldsm_x4(sb + F_QHI + qoff + kk * 32,
                    qh[kk][0], qh[kk][1], qh[kk][2], qh[kk][3]);
    }

    float m_[2] = { -1e30f, -1e30f };
    float l_[2] = { 0.f, 0.f };
    float o[8][4];
#pragma unroll
    for (int n = 0; n < 8; n++)
#pragma unroll
        for (int c = 0; c < 4; c++) o[n][c] = 0.f;

    for (int it = 0; it < LK / 64; it++) {
        const int st = it & 1;
        if (it < LK / 64 - 1) F_ISSUE(it + 1);

        // S = Q*K^T : 2 MMAs per fragment pair (q_hi only)
        float s[8][4];
#pragma unroll
        for (int j = 0; j < 8; j++)
#pragma unroll
            for (int c = 0; c < 4; c++) s[j][c] = 0.f;

        const uint32_t krow = (lane & 7) + ((lane >> 4) << 3);
#pragma unroll
        for (int kk = 0; kk < 4; kk++) {
            const uint32_t kcol = kk * 32 + (lane & 8) * 2;
#pragma unroll
            for (int jp = 0; jp < 4; jp++) {
                const uint32_t ro = (uint32_t)(jp * 16 + krow) * 144 + kcol;
                unsigned h0, h1, h2, h3, l0, l1, l2, l3;
                ldsm_x4(sb + F_KHI(st) + ro, h0, h1, h2, h3);
                ldsm_x4(sb + F_KLO(st) + ro, l0, l1, l2, l3);
                mma_f16(s[2 * jp],     qh[kk][0], qh[kk][1], qh[kk][2], qh[kk][3], h0, h1);
                mma_f16(s[2 * jp],     qh[kk][0], qh[kk][1], qh[kk][2], qh[kk][3], l0, l1);
                mma_f16(s[2 * jp + 1], qh[kk][0], qh[kk][1], qh[kk][2], qh[kk][3], h2, h3);
                mma_f16(s[2 * jp + 1], qh[kk][0], qh[kk][1], qh[kk][2], qh[kk][3], l2, l3);
            }
        }

        // Mask
        const unsigned char* msk =
            reinterpret_cast<const unsigned char*>(smem) + F_MSK(st);
#pragma unroll
        for (int j = 0; j < 8; j++) {
            const int col = j * 8 + 2 * t;
            if (msk[col])     { s[j][0] = -1e30f; s[j][2] = -1e30f; }
            if (msk[col + 1]) { s[j][1] = -1e30f; s[j][3] = -1e30f; }
        }

        // Row max (base-2 domain)
        float r0 = -1e30f, r1 = -1e30f;
#pragma unroll
        for (int j = 0; j < 8; j++) {
            r0 = fmaxf(r0, fmaxf(s[j][0], s[j][1]));
            r1 = fmaxf(r1, fmaxf(s[j][2], s[j][3]));
        }
        r0 = fmaxf(r0, __shfl_xor_sync(0xffffffffu, r0, 1));
        r0 = fmaxf(r0, __shfl_xor_sync(0xffffffffu, r0, 2));
        r1 = fmaxf(r1, __shfl_xor_sync(0xffffffffu, r1, 1));
        r1 = fmaxf(r1, __shfl_xor_sync(0xffffffffu, r1, 2));

        const float mn0 = fmaxf(m_[0], r0);
        const float mn1 = fmaxf(m_[1], r1);
        const float alpha0 = ex2f(m_[0] - mn0);
        const float alpha1 = ex2f(m_[1] - mn1);
        m_[0] = mn0; m_[1] = mn1;

        // P = 2^(S - m) computed directly in fp16x2 (these ARE the A-frags)
        unsigned ph0[8], ph1[8];
#pragma unroll
        for (int j = 0; j < 8; j++) {
            ph0[j] = h2ex2(f22h2(s[j][0] - mn0, s[j][1] - mn0));
            ph1[j] = h2ex2(f22h2(s[j][2] - mn1, s[j][3] - mn1));
        }

        // Rescale O
#pragma unroll
        for (int n = 0; n < 8; n++) {
            o[n][0] *= alpha0; o[n][1] *= alpha0;
            o[n][2] *= alpha1; o[n][3] *= alpha1;
        }

        // O += P*V ; row-sums via ones-column MMA (c_l[0]=row g, c_l[2]=row g+8)
        float c_l[4] = { 0.f, 0.f, 0.f, 0.f };
        const uint32_t vrow = (lane & 15);
        const uint32_t vcolb = (lane & 16);
#pragma unroll
        for (int kk = 0; kk < 4; kk++) {
            const unsigned a0 = ph0[2 * kk];
            const unsigned a1 = ph1[2 * kk];
            const unsigned a2 = ph0[2 * kk + 1];
            const unsigned a3 = ph1[2 * kk + 1];
            const uint32_t rbase = (uint32_t)(kk * 16 + vrow) * 144 + vcolb;
#pragma unroll
            for (int np = 0; np < 4; np++) {
                unsigned r0v, r1v, r2v, r3v;
                ldsm_x4_t(sb + F_VH(st) + rbase + np * 32, r0v, r1v, r2v, r3v);
                mma_f16(o[2 * np],     a0, a1, a2, a3, r0v, r1v);
                mma_f16(o[2 * np + 1], a0, a1, a2, a3, r2v, r3v);
            }
            mma_f16(c_l, a0, a1, a2, a3, ONESH2, ONESH2);
        }
        l_[0] = l_[0] * alpha0 + c_l[0];
        l_[1] = l_[1] * alpha1 + c_l[2];

        if (it < LK / 64 - 1) { cp_waitall(); __syncthreads(); }
    }

    // Epilogue: normalize, split, write ctx hi/lo
    const float inv0 = 1.f / l_[0];
    const float inv1 = 1.f / l_[1];
#pragma unroll
    for (int n = 0; n < 8; n++) {
        const int col = h * HD + n * 8 + 2 * t;
        const int row0 = q0 + m0 + g;
        const size_t off0 = ((size_t)b * LQ + row0) * DM + col;
        const size_t off1 = ((size_t)b * LQ + row0 + 8) * DM + col;
        unsigned hi0, lo0, hi1, lo1;
        split2(o[n][0] * inv0, o[n][1] * inv0, hi0, lo0);
        split2(o[n][2] * inv1, o[n][3] * inv1, hi1, lo1);
        *reinterpret_cast<unsigned*>(chi + off0) = hi0;
        *reinterpret_cast<unsigned*>(clo + off0) = lo0;
        *reinterpret_cast<unsigned*>(chi + off1) = hi1;
        *reinterpret_cast<unsigned*>(clo + off1) = lo1;
    }
#undef F_ISSUE
}

// ---------------------------------------------------------------------------
// Launch
// ---------------------------------------------------------------------------
extern "C" void kernel_launch(void* const* d_in, const int* in_sizes, int n_in,
                              void* d_out, int out_size)
{
    const float* query = (const float*)d_in[0];
    const float* key   = (const float*)d_in[1];
    const float* value = (const float*)d_in[2];
    const float* cos_q = (const float*)d_in[3];
    const float* sin_q = (const float*)d_in[4];
    const float* cos_k = (const float*)d_in[5];
    const float* sin_k = (const float*)d_in[6];
    const unsigned char* mask = (const unsigned char*)d_in[7];
    const float* Wq = (const float*)d_in[8];
    const float* bq = (const float*)d_in[9];
    const float* Wk = (const float*)d_in[10];
    const float* bk = (const float*)d_in[11];
    const float* Wv = (const float*)d_in[12];
    const float* bv = (const float*)d_in[13];
    const float* Wo = (const float*)d_in[14];
    const float* bo = (const float*)d_in[15];
    float* out = (float*)d_out;

    __half *pahi, *palo, *pwhi, *pwlo;
    __half *pqhi, *pkhi, *pklo, *pvh, *pchi, *pclo;
    cudaGetSymbolAddress((void**)&pahi, g_ahi);
    cudaGetSymbolAddress((void**)&palo, g_alo);
    cudaGetSymbolAddress((void**)&pwhi, g_whi);
    cudaGetSymbolAddress((void**)&pwlo, g_wlo);
    cudaGetSymbolAddress((void**)&pqhi, g_qhi);
    cudaGetSymbolAddress((void**)&pkhi, g_khi);
    cudaGetSymbolAddress((void**)&pklo, g_klo);
    cudaGetSymbolAddress((void**)&pvh,  g_vh);
    cudaGetSymbolAddress((void**)&pchi, g_chi);
    cudaGetSymbolAddress((void**)&pclo, g_clo);

    cudaFuncSetAttribute(gemm_cp_kernel<0>,
                         cudaFuncAttributeMaxDynamicSharedMemorySize, G_SMEM);
    cudaFuncSetAttribute(gemm_cp_kernel<2>,
                         cudaFuncAttributeMaxDynamicSharedMemorySize, G_SMEM);
    cudaFuncSetAttribute(gemm_cp_kernel<3>,
                         cudaFuncAttributeMaxDynamicSharedMemorySize, G_SMEM);
    cudaFuncSetAttribute(gemm_cp_kernel<4>,
                         cudaFuncAttributeMaxDynamicSharedMemorySize, G_SMEM);
    cudaFuncSetAttribute(flash_bk64_kernel,
                         cudaFuncAttributeMaxDynamicSharedMemorySize, F_SMEM);

    const int nA4 = MTOT * DM / 4;
    const int nW4 = DM * DM / 4;
    dim3 gg(DM / 128, MTOT / 256);   // (8, 32)

    // Q projection (+RoPE, hi only, scale = 0.125*log2e folded)
    split_kernel<<<(nA4 + 255) / 256, 256>>>((const float4*)query,
                                             (uint2*)pahi, (uint2*)palo, nA4);
    split_kernel<<<(nW4 + 255) / 256, 256>>>((const float4*)Wq,
                                             (uint2*)pwhi, (uint2*)pwlo, nW4);
    gemm_cp_kernel<4><<<gg, 256, G_SMEM>>>(pahi, palo, pwhi, pwlo, bq,
                                           cos_q, sin_q, QSCALE,
                                           nullptr, pqhi, nullptr);

    // K projection (+RoPE, split hi/lo)
    split_kernel<<<(nA4 + 255) / 256, 256>>>((const float4*)key,
                                             (uint2*)pahi, (uint2*)palo, nA4);
    split_kernel<<<(nW4 + 255) / 256, 256>>>((const float4*)Wk,
                                             (uint2*)pwhi, (uint2*)pwlo, nW4);
    gemm_cp_kernel<2><<<gg, 256, G_SMEM>>>(pahi, palo, pwhi, pwlo, bk,
                                           cos_k, sin_k, 1.0f,
                                           nullptr, pkhi, pklo);

    // V projection (fp16 direct)
    split_kernel<<<(nA4 + 255) / 256, 256>>>((const float4*)value,
                                             (uint2*)pahi, (uint2*)palo, nA4);
    split_kernel<<<(nW4 + 255) / 256, 256>>>((const float4*)Wv,
                                             (uint2*)pwhi, (uint2*)pwlo, nW4);
    gemm_cp_kernel<3><<<gg, 256, G_SMEM>>>(pahi, palo, pwhi, pwlo, bv,
                                           nullptr, nullptr, 1.0f,
                                           nullptr, pvh, nullptr);

    // Attention (2-MMA QK, fp16 exp, ones-column sums; writes split ctx)
    flash_bk64_kernel<<<dim3(LQ / 64, BB * NH), 128, F_SMEM>>>(
        pqhi, pkhi, pklo, pvh, mask, pchi, pclo);

    // Output projection (A = split ctx)
    split_kernel<<<(nW4 + 255) / 256, 256>>>((const float4*)Wo,
                                             (uint2*)pwhi, (uint2*)pwlo, nW4);
    gemm_cp_kernel<0><<<gg, 256, G_SMEM>>>(pchi, pclo, pwhi, pwlo, bo,
                                           nullptr, nullptr, 1.0f,
                                           out, nullptr, nullptr);
}

// round 11
// speedup vs baseline: 4.3374x; 1.1031x over previous
#include <cuda_runtime.h>
#include <cuda_fp16.h>
#include <math.h>
#include <stdint.h>

// Problem constants
#define BB   4
#define NH   16
#define HD   64
#define DM   1024
#define LQ   2048
#define LK   2048
#define MTOT (BB * LQ)

// ---------------------------------------------------------------------------
// Scratch (device globals — no allocation allowed)
// ---------------------------------------------------------------------------
__device__ __half g_ahi[MTOT * DM];
__device__ __half g_alo[MTOT * DM];
__device__ __half g_whi[DM * DM];
__device__ __half g_wlo[DM * DM];
__device__ __half g_qhi[BB * NH * LQ * HD];
__device__ __half g_khi[BB * NH * LK * HD];
__device__ __half g_vh [BB * NH * LK * HD];
__device__ __half g_chi[MTOT * DM];
__device__ __half g_clo[MTOT * DM];

// ---------------------------------------------------------------------------
// Helpers
// ---------------------------------------------------------------------------
__device__ __forceinline__ unsigned pack_h2(__half a, __half b) {
    return (unsigned)__half_as_ushort(a) | ((unsigned)__half_as_ushort(b) << 16);
}

__device__ __forceinline__ void split2(float x, float y,
                                       unsigned& hi, unsigned& lo) {
    __half hx = __float2half_rn(x);
    __half hy = __float2half_rn(y);
    __half lx = __float2half_rn(x - __half2float(hx));
    __half ly = __float2half_rn(y - __half2float(hy));
    hi = pack_h2(hx, hy);
    lo = pack_h2(lx, ly);
}

__device__ __forceinline__ float ex2f(float x) {
    float y;
    asm("ex2.approx.ftz.f32 %0, %1;" : "=f"(y) : "f"(x));
    return y;
}

// pack two floats into f16x2 (lo -> low half), then 2^x elementwise in fp16
__device__ __forceinline__ unsigned f22h2(float lo, float hi) {
    unsigned r;
    asm("cvt.rn.f16x2.f32 %0, %1, %2;" : "=r"(r) : "f"(hi), "f"(lo));
    return r;
}
__device__ __forceinline__ unsigned h2ex2(unsigned x) {
    unsigned y;
    asm("ex2.approx.f16x2 %0, %1;" : "=r"(y) : "r"(x));
    return y;
}

__device__ __forceinline__ void mma_f16(float c[4],
                                        unsigned a0, unsigned a1,
                                        unsigned a2, unsigned a3,
                                        unsigned b0, unsigned b1) {
    asm volatile(
        "mma.sync.aligned.m16n8k16.row.col.f32.f16.f16.f32 "
        "{%0,%1,%2,%3}, {%4,%5,%6,%7}, {%8,%9}, {%0,%1,%2,%3};"
        : "+f"(c[0]), "+f"(c[1]), "+f"(c[2]), "+f"(c[3])
        : "r"(a0), "r"(a1), "r"(a2), "r"(a3), "r"(b0), "r"(b1));
}

__device__ __forceinline__ uint32_t smem_u32(const void* p) {
    uint32_t a;
    asm("{ .reg .u64 t; cvta.to.shared.u64 t, %1; cvt.u32.u64 %0, t; }"
        : "=r"(a) : "l"(p));
    return a;
}

__device__ __forceinline__ void ldsm_x4(uint32_t addr, unsigned& r0,
                                        unsigned& r1, unsigned& r2,
                                        unsigned& r3) {
    asm volatile(
        "ldmatrix.sync.aligned.m8n8.x4.shared.b16 {%0,%1,%2,%3}, [%4];"
        : "=r"(r0), "=r"(r1), "=r"(r2), "=r"(r3) : "r"(addr));
}

__device__ __forceinline__ void ldsm_x4_t(uint32_t addr, unsigned& r0,
                                          unsigned& r1, unsigned& r2,
                                          unsigned& r3) {
    asm volatile(
        "ldmatrix.sync.aligned.m8n8.x4.trans.shared.b16 {%0,%1,%2,%3}, [%4];"
        : "=r"(r0), "=r"(r1), "=r"(r2), "=r"(r3) : "r"(addr));
}

__device__ __forceinline__ void cpa16(uint32_t dst, const void* src) {
    asm volatile("cp.async.cg.shared.global [%0], [%1], 16;"
                 :: "r"(dst), "l"(src) : "memory");
}
__device__ __forceinline__ void cp_commit() {
    asm volatile("cp.async.commit_group;" ::: "memory");
}
__device__ __forceinline__ void cp_waitall() {
    asm volatile("cp.async.wait_group 0;" ::: "memory");
}

#define QSCALE 0.18033688011112042f   /* 0.125 * log2(e) */
#define ONESH2 0x3C003C00u            /* half2(1.0, 1.0) */

// ---------------------------------------------------------------------------
// Pre-split kernel: 8 fp32 per thread, uint4 (16B) stores
// ---------------------------------------------------------------------------
__global__ void split_kernel(const float4* __restrict__ src,
                             uint4* __restrict__ hi,
                             uint4* __restrict__ lo, int n8)
{
    int i = blockIdx.x * blockDim.x + threadIdx.x;
    if (i >= n8) return;
    float4 v0 = src[2 * i];
    float4 v1 = src[2 * i + 1];
    uint4 h, l;
    split2(v0.x, v0.y, h.x, l.x);
    split2(v0.z, v0.w, h.y, l.y);
    split2(v1.x, v1.y, h.z, l.z);
    split2(v1.z, v1.w, h.w, l.w);
    hi[i] = h;
    lo[i] = l;
}

// ---------------------------------------------------------------------------
// Split-fp16 GEMM: 256x128 tile, 256 threads / 8 warps, warp tile 64x64.
// cp.async double-buffer + ldmatrix.
// MODE 0: C fp32 [m][n] (out projection)
// MODE 3: plain fp16 -> ohi head layout (V proj)
// MODE 4: RoPE fused, hi-only fp16 -> ohi head layout (Q and K proj)
// ---------------------------------------------------------------------------
#define G_STAGE 61440
#define G_AHI   0            /* 256 rows x 80B = 20480 */
#define G_ALO   20480
#define G_BHI   40960        /* 128 rows x 80B = 10240 */
#define G_BLO   51200
#define G_SMEM  (2 * G_STAGE)   /* 122880 */

template <int MODE>
__global__ void __launch_bounds__(256)
gemm_cp_kernel(const __half* __restrict__ Ahi, const __half* __restrict__ Alo,
               const __half* __restrict__ Whi, const __half* __restrict__ Wlo,
               const float* __restrict__ bias,
               const float* __restrict__ cosb, const float* __restrict__ sinb,
               float scale, float* __restrict__ outf,
               __half* __restrict__ ohi)
{
    extern __shared__ __align__(128) char smem[];
    const int tid  = threadIdx.x;
    const int warp = tid >> 5;
    const int lane = tid & 31;
    const int g = lane >> 2;
    const int t = lane & 3;
    const int wm = (warp & 3) * 64;       // 4 warps over M (256)
    const int wn = (warp >> 2) * 64;      // 2 warps over N (128)
    const int bm = blockIdx.y * 256;
    const int bn = blockIdx.x * 128;
    const uint32_t sb = smem_u32(smem);

    float acc[4][8][4];
#pragma unroll
    for (int i = 0; i < 4; i++)
#pragma unroll
        for (int j = 0; j < 8; j++)
#pragma unroll
            for (int c = 0; c < 4; c++) acc[i][j][c] = 0.f;

    const int lrow = tid >> 2;            // 0..63
    const int lch  = tid & 3;
#define G_ISSUE(IT)                                                          \
    do {                                                                     \
        const int kt_ = (IT) * 32;                                           \
        const uint32_t base_ = sb + ((IT) & 1) * G_STAGE;                    \
        _Pragma("unroll")                                                    \
        for (int p_ = 0; p_ < 4; p_++) {                                     \
            const int row_ = lrow + p_ * 64;                                 \
            const uint32_t d_ = row_ * 80 + lch * 16;                        \
            const size_t sa_ = (size_t)(bm + row_) * DM + kt_ + lch * 8;     \
            cpa16(base_ + G_AHI + d_, Ahi + sa_);                            \
            cpa16(base_ + G_ALO + d_, Alo + sa_);                            \
        }                                                                    \
        _Pragma("unroll")                                                    \
        for (int p_ = 0; p_ < 2; p_++) {                                     \
            const int row_ = lrow + p_ * 64;                                 \
            const uint32_t d_ = row_ * 80 + lch * 16;                        \
            const size_t sb_ = (size_t)(bn + row_) * DM + kt_ + lch * 8;     \
            cpa16(base_ + G_BHI + d_, Whi + sb_);                            \
            cpa16(base_ + G_BLO + d_, Wlo + sb_);                            \
        }                                                                    \
        cp_commit();                                                         \
    } while (0)

    G_ISSUE(0);
    cp_waitall();
    __syncthreads();

    for (int it = 0; it < 32; it++) {
        const uint32_t abase = sb + (it & 1) * G_STAGE;
        if (it < 31) G_ISSUE(it + 1);

#pragma unroll
        for (int kk = 0; kk < 2; kk++) {
            const uint32_t acol = kk * 32 + (lane & 16);
            const uint32_t arow = (lane & 15);
            unsigned ah[4][4], al[4][4];
#pragma unroll
            for (int i = 0; i < 4; i++) {
                const uint32_t ro = (uint32_t)(wm + 16 * i + arow) * 80 + acol;
                ldsm_x4(abase + G_AHI + ro, ah[i][0], ah[i][1], ah[i][2], ah[i][3]);
                ldsm_x4(abase + G_ALO + ro, al[i][0], al[i][1], al[i][2], al[i][3]);
            }
            const uint32_t brow = (lane & 7) + ((lane >> 4) << 3);
            const uint32_t bcol = kk * 32 + (lane & 8) * 2;
#pragma unroll
            for (int jp = 0; jp < 4; jp++) {
                const uint32_t ro = (uint32_t)(wn + 16 * jp + brow) * 80 + bcol;
                unsigned h0, h1, h2, h3, l0, l1, l2, l3;
                ldsm_x4(abase + G_BHI + ro, h0, h1, h2, h3);
                ldsm_x4(abase + G_BLO + ro, l0, l1, l2, l3);
#pragma unroll
                for (int i = 0; i < 4; i++) {
                    mma_f16(acc[i][2 * jp],     ah[i][0], ah[i][1], ah[i][2], ah[i][3], h0, h1);
                    mma_f16(acc[i][2 * jp],     ah[i][0], ah[i][1], ah[i][2], ah[i][3], l0, l1);
                    mma_f16(acc[i][2 * jp],     al[i][0], al[i][1], al[i][2], al[i][3], h0, h1);
                    mma_f16(acc[i][2 * jp + 1], ah[i][0], ah[i][1], ah[i][2], ah[i][3], h2, h3);
                    mma_f16(acc[i][2 * jp + 1], ah[i][0], ah[i][1], ah[i][2], ah[i][3], l2, l3);
                    mma_f16(acc[i][2 * jp + 1], al[i][0], al[i][1], al[i][2], al[i][3], h2, h3);
                }
            }
        }
        if (it < 31) { cp_waitall(); __syncthreads(); }
    }

    // ---- Epilogues ----
    const int h = (bn + wn) >> 6;   // head for this warp's N-tile (N=64 = 1 head)

    if (MODE == 0) {
#pragma unroll
        for (int i = 0; i < 4; i++) {
#pragma unroll
            for (int j = 0; j < 8; j++) {
                const int n = bn + wn + 8 * j + 2 * t;
                const float b0 = bias[n];
                const float b1 = bias[n + 1];
#pragma unroll
                for (int half = 0; half < 2; half++) {
                    const int m = bm + wm + 16 * i + g + half * 8;
                    float2 val;
                    val.x = acc[i][j][half * 2 + 0] + b0;
                    val.y = acc[i][j][half * 2 + 1] + b1;
                    *reinterpret_cast<float2*>(outf + (size_t)m * DM + n) = val;
                }
            }
        }
    } else if (MODE == 4) {
        // RoPE, hi-only fp16. Pair: col dd (j<4) with col dd+32 (j+4).
#pragma unroll
        for (int i = 0; i < 4; i++) {
#pragma unroll
            for (int half = 0; half < 2; half++) {
                const int m = bm + wm + 16 * i + g + half * 8;
                const int b = m >> 11;
                const int l = m & (LQ - 1);
                const size_t rowoff = (((size_t)(b * NH + h)) * LQ + l) * HD;
                const float* cr = cosb + ((size_t)b * LQ + l) * HD;
                const float* sr = sinb + ((size_t)b * LQ + l) * HD;
#pragma unroll
                for (int j = 0; j < 4; j++) {
                    const int dd = 8 * j + 2 * t;
                    const int n1 = bn + wn + dd;
                    float x1a = acc[i][j][half * 2 + 0] + bias[n1];
                    float x1b = acc[i][j][half * 2 + 1] + bias[n1 + 1];
                    float x2a = acc[i][j + 4][half * 2 + 0] + bias[n1 + 32];
                    float x2b = acc[i][j + 4][half * 2 + 1] + bias[n1 + 33];
                    float y1a = (x1a * cr[dd]      - x2a * sr[dd])      * scale;
                    float y1b = (x1b * cr[dd + 1]  - x2b * sr[dd + 1])  * scale;
                    float y2a = (x2a * cr[dd + 32] + x1a * sr[dd + 32]) * scale;
                    float y2b = (x2b * cr[dd + 33] + x1b * sr[dd + 33]) * scale;
                    *reinterpret_cast<unsigned*>(ohi + rowoff + dd) =
                        pack_h2(__float2half_rn(y1a), __float2half_rn(y1b));
                    *reinterpret_cast<unsigned*>(ohi + rowoff + dd + 32) =
                        pack_h2(__float2half_rn(y2a), __float2half_rn(y2b));
                }
            }
        }
    } else {  // MODE 3: plain fp16 head layout (V)
#pragma unroll
        for (int i = 0; i < 4; i++) {
#pragma unroll
            for (int half = 0; half < 2; half++) {
                const int m = bm + wm + 16 * i + g + half * 8;
                const int b = m >> 11;
                const int l = m & (LQ - 1);
                const size_t rowoff = (((size_t)(b * NH + h)) * LQ + l) * HD;
#pragma unroll
                for (int j = 0; j < 8; j++) {
                    const int dd = 8 * j + 2 * t;
                    const int n = bn + wn + dd;
                    float vx = acc[i][j][half * 2 + 0] + bias[n];
                    float vy = acc[i][j][half * 2 + 1] + bias[n + 1];
                    *reinterpret_cast<unsigned*>(ohi + rowoff + dd) =
                        pack_h2(__float2half_rn(vx), __float2half_rn(vy));
                }
            }
        }
    }
#undef G_ISSUE
}

// ---------------------------------------------------------------------------
// Flash attention, BK=64. Q and K both plain fp16 (single-MMA QK^T).
// fp16x2 ex2 softmax; row sums via ones-column MMA. Writes split ctx.
// One block = (b,h) x 64 Q rows; 4 warps x 16 rows; 32 iters of 64 keys.
// ---------------------------------------------------------------------------
#define F_STG   18496
#define F_QHI   0
#define F_KHI(s) (9216 + (s) * F_STG)
#define F_VH(s)  (F_KHI(s) + 9216)
#define F_MSK(s) (F_KHI(s) + 18432)
#define F_SMEM  (9216 + 2 * F_STG)   /* 46208 */

__global__ void __launch_bounds__(128)
flash_bk64_kernel(const __half* __restrict__ qhi,
                  const __half* __restrict__ khi,
                  const __half* __restrict__ vh,
                  const unsigned char* __restrict__ mask,
                  __half* __restrict__ chi, __half* __restrict__ clo)
{
    extern __shared__ __align__(128) char smem[];
    const int tid  = threadIdx.x;
    const int warp = tid >> 5;
    const int lane = tid & 31;
    const int g = lane >> 2;
    const int t = lane & 3;
    const int m0 = warp * 16;

    const int bh = blockIdx.y;
    const int b  = bh >> 4;
    const int h  = bh & 15;
    const int q0 = blockIdx.x * 64;
    const uint32_t sb = smem_u32(smem);

    const __half* qh_g = qhi + (((size_t)bh) * LQ + q0) * HD;
    const size_t kvbase = ((size_t)bh) * LK * HD;

    const int lrow = tid >> 3;   // 0..15
    const int lch  = tid & 7;

#define F_ISSUE(IT)                                                          \
    do {                                                                     \
        const int kt_ = (IT) * 64;                                           \
        const int st_ = (IT) & 1;                                            \
        _Pragma("unroll")                                                    \
        for (int p_ = 0; p_ < 4; p_++) {                                     \
            const int row_ = lrow + p_ * 16;                                 \
            const uint32_t d_ = row_ * 144 + lch * 16;                       \
            const size_t s_ = kvbase + (size_t)(kt_ + row_) * HD + lch * 8;  \
            cpa16(sb + F_KHI(st_) + d_, khi + s_);                           \
            cpa16(sb + F_VH(st_)  + d_, vh  + s_);                           \
        }                                                                    \
        if (tid < 4)                                                         \
            cpa16(sb + F_MSK(st_) + tid * 16,                                \
                  mask + (size_t)b * LK + kt_ + tid * 16);                   \
        cp_commit();                                                         \
    } while (0)

    // Prologue: Q tile + stage 0
#pragma unroll
    for (int p = 0; p < 4; p++) {
        const int row = lrow + p * 16;
        const uint32_t d = row * 144 + lch * 16;
        cpa16(sb + F_QHI + d, qh_g + (size_t)row * HD + lch * 8);
    }
    F_ISSUE(0);
    cp_waitall();
    __syncthreads();

    unsigned qh[4][4];
    {
        const uint32_t qoff = (uint32_t)(m0 + (lane & 15)) * 144 + (lane & 16);
#pragma unroll
        for (int kk = 0; kk < 4; kk++)
            ldsm_x4(sb + F_QHI + qoff + kk * 32,
                    qh[kk][0], qh[kk][1], qh[kk][2], qh[kk][3]);
    }

    float m_[2] = { -1e30f, -1e30f };
    float l_[2] = { 0.f, 0.f };
    float o[8][4];
#pragma unroll
    for (int n = 0; n < 8; n++)
#pragma unroll
        for (int c = 0; c < 4; c++) o[n][c] = 0.f;

    for (int it = 0; it < LK / 64; it++) {
        const int st = it & 1;
        if (it < LK / 64 - 1) F_ISSUE(it + 1);

        // S = Q*K^T : single fp16 MMA per fragment pair
        float s[8][4];
#pragma unroll
        for (int j = 0; j < 8; j++)
#pragma unroll
            for (int c = 0; c < 4; c++) s[j][c] = 0.f;

        const uint32_t krow = (lane & 7) + ((lane >> 4) << 3);
#pragma unroll
        for (int kk = 0; kk < 4; kk++) {
            const uint32_t kcol = kk * 32 + (lane & 8) * 2;
#pragma unroll
            for (int jp = 0; jp < 4; jp++) {
                const uint32_t ro = (uint32_t)(jp * 16 + krow) * 144 + kcol;
                unsigned h0, h1, h2, h3;
                ldsm_x4(sb + F_KHI(st) + ro, h0, h1, h2, h3);
                mma_f16(s[2 * jp],     qh[kk][0], qh[kk][1], qh[kk][2], qh[kk][3], h0, h1);
                mma_f16(s[2 * jp + 1], qh[kk][0], qh[kk][1], qh[kk][2], qh[kk][3], h2, h3);
            }
        }

        // Mask
        const unsigned char* msk =
            reinterpret_cast<const unsigned char*>(smem) + F_MSK(st);
#pragma unroll
        for (int j = 0; j < 8; j++) {
            const int col = j * 8 + 2 * t;
            if (msk[col])     { s[j][0] = -1e30f; s[j][2] = -1e30f; }
            if (msk[col + 1]) { s[j][1] = -1e30f; s[j][3] = -1e30f; }
        }

        // Row max (base-2 domain)
        float r0 = -1e30f, r1 = -1e30f;
#pragma unroll
        for (int j = 0; j < 8; j++) {
            r0 = fmaxf(r0, fmaxf(s[j][0], s[j][1]));
            r1 = fmaxf(r1, fmaxf(s[j][2], s[j][3]));
        }
        r0 = fmaxf(r0, __shfl_xor_sync(0xffffffffu, r0, 1));
        r0 = fmaxf(r0, __shfl_xor_sync(0xffffffffu, r0, 2));
        r1 = fmaxf(r1, __shfl_xor_sync(0xffffffffu, r1, 1));
        r1 = fmaxf(r1, __shfl_xor_sync(0xffffffffu, r1, 2));

        const float mn0 = fmaxf(m_[0], r0);
        const float mn1 = fmaxf(m_[1], r1);
        const float alpha0 = ex2f(m_[0] - mn0);
        const float alpha1 = ex2f(m_[1] - mn1);
        m_[0] = mn0; m_[1] = mn1;

        // P = 2^(S - m) in fp16x2 (these ARE the A-frags)
        unsigned ph0[8], ph1[8];
#pragma unroll
        for (int j = 0; j < 8; j++) {
            ph0[j] = h2ex2(f22h2(s[j][0] - mn0, s[j][1] - mn0));
            ph1[j] = h2ex2(f22h2(s[j][2] - mn1, s[j][3] - mn1));
        }

        // Rescale O
#pragma unroll
        for (int n = 0; n < 8; n++) {
            o[n][0] *= alpha0; o[n][1] *= alpha0;
            o[n][2] *= alpha1; o[n][3] *= alpha1;
        }

        // O += P*V ; row sums via ones-column MMA
        float c_l[4] = { 0.f, 0.f, 0.f, 0.f };
        const uint32_t vrow = (lane & 15);
        const uint32_t vcolb = (lane & 16);
#pragma unroll
        for (int kk = 0; kk < 4; kk++) {
            const unsigned a0 = ph0[2 * kk];
            const unsigned a1 = ph1[2 * kk];
            const unsigned a2 = ph0[2 * kk + 1];
            const unsigned a3 = ph1[2 * kk + 1];
            const uint32_t rbase = (uint32_t)(kk * 16 + vrow) * 144 + vcolb;
#pragma unroll
            for (int np = 0; np < 4; np++) {
                unsigned r0v, r1v, r2v, r3v;
                ldsm_x4_t(sb + F_VH(st) + rbase + np * 32, r0v, r1v, r2v, r3v);
                mma_f16(o[2 * np],     a0, a1, a2, a3, r0v, r1v);
                mma_f16(o[2 * np + 1], a0, a1, a2, a3, r2v, r3v);
            }
            mma_f16(c_l, a0, a1, a2, a3, ONESH2, ONESH2);
        }
        l_[0] = l_[0] * alpha0 + c_l[0];
        l_[1] = l_[1] * alpha1 + c_l[2];

        if (it < LK / 64 - 1) { cp_waitall(); __syncthreads(); }
    }

    // Epilogue: normalize, split, write ctx hi/lo
    const float inv0 = 1.f / l_[0];
    const float inv1 = 1.f / l_[1];
#pragma unroll
    for (int n = 0; n < 8; n++) {
        const int col = h * HD + n * 8 + 2 * t;
        const int row0 = q0 + m0 + g;
        const size_t off0 = ((size_t)b * LQ + row0) * DM + col;
        const size_t off1 = ((size_t)b * LQ + row0 + 8) * DM + col;
        unsigned hi0, lo0, hi1, lo1;
        split2(o[n][0] * inv0, o[n][1] * inv0, hi0, lo0);
        split2(o[n][2] * inv1, o[n][3] * inv1, hi1, lo1);
        *reinterpret_cast<unsigned*>(chi + off0) = hi0;
        *reinterpret_cast<unsigned*>(clo + off0) = lo0;
        *reinterpret_cast<unsigned*>(chi + off1) = hi1;
        *reinterpret_cast<unsigned*>(clo + off1) = lo1;
    }
#undef F_ISSUE
}

// ---------------------------------------------------------------------------
// Launch
// ---------------------------------------------------------------------------
extern "C" void kernel_launch(void* const* d_in, const int* in_sizes, int n_in,
                              void* d_out, int out_size)
{
    const float* query = (const float*)d_in[0];
    const float* key   = (const float*)d_in[1];
    const float* value = (const float*)d_in[2];
    const float* cos_q = (const float*)d_in[3];
    const float* sin_q = (const float*)d_in[4];
    const float* cos_k = (const float*)d_in[5];
    const float* sin_k = (const float*)d_in[6];
    const unsigned char* mask = (const unsigned char*)d_in[7];
    const float* Wq = (const float*)d_in[8];
    const float* bq = (const float*)d_in[9];
    const float* Wk = (const float*)d_in[10];
    const float* bk = (const float*)d_in[11];
    const float* Wv = (const float*)d_in[12];
    const float* bv = (const float*)d_in[13];
    const float* Wo = (const float*)d_in[14];
    const float* bo = (const float*)d_in[15];
    float* out = (float*)d_out;

    __half *pahi, *palo, *pwhi, *pwlo;
    __half *pqhi, *pkhi, *pvh, *pchi, *pclo;
    cudaGetSymbolAddress((void**)&pahi, g_ahi);
    cudaGetSymbolAddress((void**)&palo, g_alo);
    cudaGetSymbolAddress((void**)&pwhi, g_whi);
    cudaGetSymbolAddress((void**)&pwlo, g_wlo);
    cudaGetSymbolAddress((void**)&pqhi, g_qhi);
    cudaGetSymbolAddress((void**)&pkhi, g_khi);
    cudaGetSymbolAddress((void**)&pvh,  g_vh);
    cudaGetSymbolAddress((void**)&pchi, g_chi);
    cudaGetSymbolAddress((void**)&pclo, g_clo);

    cudaFuncSetAttribute(gemm_cp_kernel<0>,
                         cudaFuncAttributeMaxDynamicSharedMemorySize, G_SMEM);
    cudaFuncSetAttribute(gemm_cp_kernel<3>,
                         cudaFuncAttributeMaxDynamicSharedMemorySize, G_SMEM);
    cudaFuncSetAttribute(gemm_cp_kernel<4>,
                         cudaFuncAttributeMaxDynamicSharedMemorySize, G_SMEM);
    cudaFuncSetAttribute(flash_bk64_kernel,
                         cudaFuncAttributeMaxDynamicSharedMemorySize, F_SMEM);

    const int nA8 = MTOT * DM / 8;
    const int nW8 = DM * DM / 8;
    dim3 gg(DM / 128, MTOT / 256);   // (8, 32)

    // Q projection (+RoPE, hi only, scale = 0.125*log2e folded)
    split_kernel<<<(nA8 + 255) / 256, 256>>>((const float4*)query,
                                             (uint4*)pahi, (uint4*)palo, nA8);
    split_kernel<<<(nW8 + 255) / 256, 256>>>((const float4*)Wq,
                                             (uint4*)pwhi, (uint4*)pwlo, nW8);
    gemm_cp_kernel<4><<<gg, 256, G_SMEM>>>(pahi, palo, pwhi, pwlo, bq,
                                           cos_q, sin_q, QSCALE,
                                           nullptr, pqhi);

    // K projection (+RoPE, hi only, scale 1)
    split_kernel<<<(nA8 + 255) / 256, 256>>>((const float4*)key,
                                             (uint4*)pahi, (uint4*)palo, nA8);
    split_kernel<<<(nW8 + 255) / 256, 256>>>((const float4*)Wk,
                                             (uint4*)pwhi, (uint4*)pwlo, nW8);
    gemm_cp_kernel<4><<<gg, 256, G_SMEM>>>(pahi, palo, pwhi, pwlo, bk,
                                           cos_k, sin_k, 1.0f,
                                           nullptr, pkhi);

    // V projection (fp16 direct)
    split_kernel<<<(nA8 + 255) / 256, 256>>>((const float4*)value,
                                             (uint4*)pahi, (uint4*)palo, nA8);
    split_kernel<<<(nW8 + 255) / 256, 256>>>((const float4*)Wv,
                                             (uint4*)pwhi, (uint4*)pwlo, nW8);
    gemm_cp_kernel<3><<<gg, 256, G_SMEM>>>(pahi, palo, pwhi, pwlo, bv,
                                           nullptr, nullptr, 1.0f,
                                           nullptr, pvh);

    // Attention (single-MMA QK, fp16 exp, ones-column sums; writes split ctx)
    flash_bk64_kernel<<<dim3(LQ / 64, BB * NH), 128, F_SMEM>>>(
        pqhi, pkhi, pvh, mask, pchi, pclo);

    // Output projection (A = split ctx)
    split_kernel<<<(nW8 + 255) / 256, 256>>>((const float4*)Wo,
                                             (uint4*)pwhi, (uint4*)pwlo, nW8);
    gemm_cp_kernel<0><<<gg, 256, G_SMEM>>>(pchi, pclo, pwhi, pwlo, bo,
                                           nullptr, nullptr, 1.0f,
                                           out, nullptr);
}